// round 1
// baseline (speedup 1.0000x reference)
#include <cuda_runtime.h>
#include <math.h>

#define N_NODESC 100000
#define N_EDGESC 1600000
#define HID 128
#define NGRAPH 256
#define NLAYER 3

// ---------------- scratch (static device globals; no allocation) ----------------
__device__ float g_h[(size_t)N_NODESC * HID];    // GEMM output per layer
__device__ float g_x[(size_t)N_NODESC * HID];    // layer activations
__device__ float g_dis[N_NODESC];                // 1/sqrt(deg)
__device__ int   g_off[N_NODESC + 1];            // CSR offsets (by dst)
__device__ int   g_cur[N_NODESC];                // bucket cursors
__device__ int   g_srcb[N_EDGESC];               // bucketed src ids
__device__ float g_scg[NGRAPH * HID];
__device__ float g_fcg[NGRAPH * HID];
__device__ float g_z[NGRAPH * HID];
__device__ float g_scn[NGRAPH * HID];
__device__ float g_fcn[NGRAPH * HID];
__device__ float g_loss[2 * NGRAPH];

// ---------------- CSR build ----------------
__global__ void k_zero_counts() {
    int i = blockIdx.x * blockDim.x + threadIdx.x;
    if (i <= N_NODESC) g_off[i] = 0;
}

__global__ void k_hist(const int* __restrict__ dst) {
    for (int e = blockIdx.x * blockDim.x + threadIdx.x; e < N_EDGESC;
         e += gridDim.x * blockDim.x)
        atomicAdd(&g_off[dst[e]], 1);
}

// single-block exclusive scan of counts -> offsets (+ cursors); g_off[N]=E
__global__ void k_scan() {
    __shared__ int warp_sums[32];
    __shared__ int s_carry;
    int t = threadIdx.x;
    int lane = t & 31, w = t >> 5;
    if (t == 0) s_carry = 0;
    __syncthreads();
    for (int base = 0; base < N_NODESC; base += 1024) {
        int idx = base + t;
        int v = (idx < N_NODESC) ? g_off[idx] : 0;
        int x = v;
#pragma unroll
        for (int off = 1; off < 32; off <<= 1) {
            int n = __shfl_up_sync(0xffffffffu, x, off);
            if (lane >= off) x += n;
        }
        if (lane == 31) warp_sums[w] = x;
        __syncthreads();
        if (w == 0) {
            int y = warp_sums[lane];
#pragma unroll
            for (int off = 1; off < 32; off <<= 1) {
                int n = __shfl_up_sync(0xffffffffu, y, off);
                if (lane >= off) y += n;
            }
            warp_sums[lane] = y;
        }
        __syncthreads();
        int inc = x + ((w > 0) ? warp_sums[w - 1] : 0);
        int exc = inc - v + s_carry;
        if (idx < N_NODESC) { g_off[idx] = exc; g_cur[idx] = exc; }
        __syncthreads();
        if (t == 1023) s_carry += inc;
        __syncthreads();
    }
    if (t == 0) g_off[N_NODESC] = s_carry;
}

__global__ void k_dis() {
    int i = blockIdx.x * blockDim.x + threadIdx.x;
    if (i < N_NODESC)
        g_dis[i] = rsqrtf((float)(g_off[i + 1] - g_off[i]) + 1.0f);
}

__global__ void k_bucket(const int* __restrict__ src, const int* __restrict__ dst) {
    for (int e = blockIdx.x * blockDim.x + threadIdx.x; e < N_EDGESC;
         e += gridDim.x * blockDim.x) {
        int d = dst[e];
        int slot = atomicAdd(&g_cur[d], 1);
        g_srcb[slot] = src[e];
    }
}

// ---------------- GEMM: H = X @ W   (X [nrows,128], W [128,128]) ----------------
// 128-row x 128-col tile per block, 256 threads, 8x8 microtile.
#define GEMM_SMEM ((128 * 129 + 128 * 128) * 4)
__global__ void k_gemm(const float* __restrict__ Xext, int use_internal,
                       const float* __restrict__ W, int nrows) {
    extern __shared__ float sm[];
    float* Xs = sm;               // [128][129] (padded rows: conflict-free)
    float* Ws = sm + 128 * 129;   // [128][128]
    const float* X = use_internal ? (const float*)g_x : Xext;
    int tid = threadIdx.x;
    int r0 = blockIdx.x * 128;
    for (int i = tid; i < 4096; i += 256)
        ((float4*)Ws)[i] = ((const float4*)W)[i];
    for (int i = tid; i < 4096; i += 256) {
        int row = i >> 5;
        int q = i & 31;
        float4 v;
        if (r0 + row < nrows) v = ((const float4*)(X + (size_t)(r0 + row) * HID))[q];
        else v = make_float4(0.f, 0.f, 0.f, 0.f);
        float* dp = Xs + row * 129 + q * 4;
        dp[0] = v.x; dp[1] = v.y; dp[2] = v.z; dp[3] = v.w;
    }
    __syncthreads();
    int tx = tid & 15, ty = tid >> 4;
    float acc[8][8];
#pragma unroll
    for (int i = 0; i < 8; i++)
#pragma unroll
        for (int j = 0; j < 8; j++) acc[i][j] = 0.f;
    const float4* Ws4 = (const float4*)Ws;
#pragma unroll 4
    for (int k = 0; k < 128; ++k) {
        float a[8], bb[8];
#pragma unroll
        for (int i = 0; i < 4; i++) {
            a[i]     = Xs[(ty * 4 + i) * 129 + k];
            a[4 + i] = Xs[(64 + ty * 4 + i) * 129 + k];
        }
        float4 b0 = Ws4[k * 32 + tx];
        float4 b1 = Ws4[k * 32 + 16 + tx];
        bb[0] = b0.x; bb[1] = b0.y; bb[2] = b0.z; bb[3] = b0.w;
        bb[4] = b1.x; bb[5] = b1.y; bb[6] = b1.z; bb[7] = b1.w;
#pragma unroll
        for (int i = 0; i < 8; i++)
#pragma unroll
            for (int j = 0; j < 8; j++) acc[i][j] = fmaf(a[i], bb[j], acc[i][j]);
    }
#pragma unroll
    for (int i = 0; i < 8; i++) {
        int row = r0 + ((i < 4) ? (ty * 4 + i) : (64 + ty * 4 + (i - 4)));
        if (row < nrows) {
            float4 v0 = make_float4(acc[i][0], acc[i][1], acc[i][2], acc[i][3]);
            float4 v1 = make_float4(acc[i][4], acc[i][5], acc[i][6], acc[i][7]);
            *(float4*)(g_h + (size_t)row * HID + tx * 4) = v0;
            *(float4*)(g_h + (size_t)row * HID + 64 + tx * 4) = v1;
        }
    }
}

// ---------------- fused aggregation: x = relu(segsum + self + bias) ----------------
// one warp per node; lanes own 4 contiguous cols (float4). No atomics.
__global__ void k_agg(const float* __restrict__ bias) {
    int node = (blockIdx.x * blockDim.x + threadIdx.x) >> 5;
    int lane = threadIdx.x & 31;
    if (node >= N_NODESC) return;
    float dd = g_dis[node];
    int beg = g_off[node], end = g_off[node + 1];
    float ax = 0.f, ay = 0.f, az = 0.f, aw = 0.f;
    int e = beg;
    for (; e + 1 < end; e += 2) {
        int s0 = g_srcb[e];
        int s1 = g_srcb[e + 1];
        float w0 = g_dis[s0] * dd;
        float w1 = g_dis[s1] * dd;
        float4 h0 = *(const float4*)(g_h + (size_t)s0 * HID + lane * 4);
        float4 h1 = *(const float4*)(g_h + (size_t)s1 * HID + lane * 4);
        ax = fmaf(h0.x, w0, ax); ay = fmaf(h0.y, w0, ay);
        az = fmaf(h0.z, w0, az); aw = fmaf(h0.w, w0, aw);
        ax = fmaf(h1.x, w1, ax); ay = fmaf(h1.y, w1, ay);
        az = fmaf(h1.z, w1, az); aw = fmaf(h1.w, w1, aw);
    }
    if (e < end) {
        int s0 = g_srcb[e];
        float w0 = g_dis[s0] * dd;
        float4 h0 = *(const float4*)(g_h + (size_t)s0 * HID + lane * 4);
        ax = fmaf(h0.x, w0, ax); ay = fmaf(h0.y, w0, ay);
        az = fmaf(h0.z, w0, az); aw = fmaf(h0.w, w0, aw);
    }
    float4 hd = *(const float4*)(g_h + (size_t)node * HID + lane * 4);
    float sn = dd * dd;
    float4 bb = *(const float4*)(bias + lane * 4);
    ax = fmaxf(fmaf(hd.x, sn, ax) + bb.x, 0.f);
    ay = fmaxf(fmaf(hd.y, sn, ay) + bb.y, 0.f);
    az = fmaxf(fmaf(hd.z, sn, az) + bb.z, 0.f);
    aw = fmaxf(fmaf(hd.w, sn, aw) + bb.w, 0.f);
    *(float4*)(g_x + (size_t)node * HID + lane * 4) = make_float4(ax, ay, az, aw);
}

// ---------------- pooling ----------------
__global__ void k_zero_pool() {
    int i = blockIdx.x * blockDim.x + threadIdx.x;
    if (i < NGRAPH * HID) { g_scg[i] = 0.f; g_fcg[i] = 0.f; }
}

__global__ void k_pool(const int* __restrict__ batch, int which) {
    long i = (long)blockIdx.x * blockDim.x + threadIdx.x;
    if (i >= (long)N_NODESC * HID) return;
    int node = (int)(i >> 7), c = (int)(i & 127);
    float* G = which ? g_fcg : g_scg;
    atomicAdd(&G[batch[node] * HID + c], g_x[i]);
}

// ---------------- head: z = relu(concat(g)@fc1+b); normalize g ----------------
__global__ void k_head(const float* __restrict__ fc1W, const float* __restrict__ fc1b) {
    int b = blockIdx.x, t = threadIdx.x;  // 128 threads
    __shared__ float s[256];
    __shared__ float red[128];
    __shared__ float inv_ns, inv_nf;
    s[t] = g_scg[b * HID + t];
    s[128 + t] = g_fcg[b * HID + t];
    __syncthreads();
    red[t] = s[t] * s[t];
    __syncthreads();
    for (int off = 64; off > 0; off >>= 1) {
        if (t < off) red[t] += red[t + off];
        __syncthreads();
    }
    if (t == 0) inv_ns = 1.0f / fmaxf(sqrtf(red[0]), 1e-12f);
    __syncthreads();
    red[t] = s[128 + t] * s[128 + t];
    __syncthreads();
    for (int off = 64; off > 0; off >>= 1) {
        if (t < off) red[t] += red[t + off];
        __syncthreads();
    }
    if (t == 0) inv_nf = 1.0f / fmaxf(sqrtf(red[0]), 1e-12f);
    __syncthreads();
    float acc = 0.f;
#pragma unroll 8
    for (int k = 0; k < 256; k++) acc = fmaf(s[k], fc1W[k * HID + t], acc);
    acc += fc1b[t];
    g_z[b * HID + t] = fmaxf(acc, 0.f);
    g_scn[b * HID + t] = s[t] * inv_ns;
    g_fcn[b * HID + t] = s[128 + t] * inv_nf;
}

// ---------------- contrastive row losses ----------------
__global__ void k_loss() {
    int i = blockIdx.x, j = threadIdx.x;  // 256 threads
    __shared__ float sni[HID], fni[HID];
    __shared__ float red[256];
    __shared__ float diag_sc, diag_fc, Msc, Mfc, Ssc, Sfc;
    if (j < HID) { sni[j] = g_scn[i * HID + j]; fni[j] = g_fcn[i * HID + j]; }
    __syncthreads();
    float dsf = 0.f, dss = 0.f, dfs = 0.f, dff = 0.f;
    const float* srow = &g_scn[j * HID];
    const float* frow = &g_fcn[j * HID];
#pragma unroll 4
    for (int k = 0; k < HID; k++) {
        float sj = srow[k], fj = frow[k], si = sni[k], fi = fni[k];
        dsf = fmaf(si, fj, dsf);
        dss = fmaf(si, sj, dss);
        dfs = fmaf(fi, sj, dfs);
        dff = fmaf(fi, fj, dff);
    }
    const float tt = 2.0f;          // 1/TEMPERATURE
    float e1 = dsf * tt;
    float e2 = (j == i) ? 0.f : 0.8f * tt * dss;
    float f1 = dfs * tt;
    float f2 = (j == i) ? 0.f : 0.8f * tt * dff;
    if (j == i) { diag_sc = e1; diag_fc = f1; }
    // sc: max then sumexp
    red[j] = fmaxf(e1, e2);
    __syncthreads();
    for (int off = 128; off > 0; off >>= 1) {
        if (j < off) red[j] = fmaxf(red[j], red[j + off]);
        __syncthreads();
    }
    if (j == 0) Msc = red[0];
    __syncthreads();
    red[j] = expf(e1 - Msc) + expf(e2 - Msc);
    __syncthreads();
    for (int off = 128; off > 0; off >>= 1) {
        if (j < off) red[j] += red[j + off];
        __syncthreads();
    }
    if (j == 0) Ssc = red[0];
    __syncthreads();
    // fc
    red[j] = fmaxf(f1, f2);
    __syncthreads();
    for (int off = 128; off > 0; off >>= 1) {
        if (j < off) red[j] = fmaxf(red[j], red[j + off]);
        __syncthreads();
    }
    if (j == 0) Mfc = red[0];
    __syncthreads();
    red[j] = expf(f1 - Mfc) + expf(f2 - Mfc);
    __syncthreads();
    for (int off = 128; off > 0; off >>= 1) {
        if (j < off) red[j] += red[j + off];
        __syncthreads();
    }
    if (j == 0) {
        Sfc = red[0];
        g_loss[i] = (Msc + logf(Ssc)) - diag_sc;
        g_loss[NGRAPH + i] = (Mfc + logf(Sfc)) - diag_fc;
    }
}

// ---------------- final: classifier logits + log_softmax + scalar ----------------
__global__ void k_final(const float* __restrict__ fc2W, const float* __restrict__ fc2b,
                        float* __restrict__ out) {
    __shared__ float red[256];
    __shared__ float scalar;
    int t = threadIdx.x;
    red[t] = g_loss[t] + g_loss[NGRAPH + t];
    __syncthreads();
    for (int off = 128; off > 0; off >>= 1) {
        if (t < off) red[t] += red[t + off];
        __syncthreads();
    }
    if (t == 0) scalar = red[0] / (2.0f * NGRAPH);
    __syncthreads();
    float l0 = fc2b[0], l1 = fc2b[1];
    const float* z = &g_z[t * HID];
#pragma unroll 4
    for (int k = 0; k < HID; k++) {
        float zv = z[k];
        l0 = fmaf(zv, fc2W[2 * k], l0);
        l1 = fmaf(zv, fc2W[2 * k + 1], l1);
    }
    float m = fmaxf(l0, l1);
    float lse = m + logf(expf(l0 - m) + expf(l1 - m));
    out[2 * t] = l0 - lse + scalar;
    out[2 * t + 1] = l1 - lse + scalar;
}

// ---------------- host side ----------------
static void run_branch(const float* x_in, const int* ei, const float* W,
                       const float* b, const int* batch, int which) {
    const int* src = ei;
    const int* dst = ei + N_EDGESC;
    k_zero_counts<<<(N_NODESC + 256) / 256, 256>>>();
    k_hist<<<2048, 256>>>(dst);
    k_scan<<<1, 1024>>>();
    k_dis<<<(N_NODESC + 255) / 256, 256>>>();
    k_bucket<<<2048, 256>>>(src, dst);
    for (int l = 0; l < NLAYER; ++l) {
        k_gemm<<<(N_NODESC + 127) / 128, 256, GEMM_SMEM>>>(
            x_in, l > 0 ? 1 : 0, W + (size_t)l * HID * HID, N_NODESC);
        k_agg<<<(N_NODESC * 32 + 255) / 256, 256>>>(b + (size_t)l * HID);
    }
    long tot = (long)N_NODESC * HID;
    k_pool<<<(unsigned)((tot + 255) / 256), 256>>>(batch, which);
}

extern "C" void kernel_launch(void* const* d_in, const int* in_sizes, int n_in,
                              void* d_out, int out_size) {
    const float *sc_x = 0, *fc_x = 0, *sc_W = 0, *sc_b = 0, *fc_W = 0, *fc_b = 0;
    const float *fc1W = 0, *fc1b = 0, *fc2W = 0, *fc2b = 0;
    const int *sc_ei = 0, *fc_ei = 0, *batch = 0;
    for (int i = 0; i < n_in; i++) {
        long s = in_sizes[i];
        const void* p = d_in[i];
        if (s == (long)N_NODESC * HID) {           // 12,800,000: sc_x then fc_x
            if (!sc_x) sc_x = (const float*)p; else fc_x = (const float*)p;
        } else if (s == 2L * N_EDGESC) {           // 3,200,000: sc_ei then fc_ei
            if (!sc_ei) sc_ei = (const int*)p; else fc_ei = (const int*)p;
        } else if (s == N_NODESC) {                // 100,000: batch
            batch = (const int*)p;
        } else if (s == (long)NLAYER * HID * HID) {  // 49,152: sc_W then fc_W
            if (!sc_W) sc_W = (const float*)p; else fc_W = (const float*)p;
        } else if (s == (long)NLAYER * HID) {      // 384: sc_b then fc_b
            if (!sc_b) sc_b = (const float*)p; else fc_b = (const float*)p;
        } else if (s == 2L * HID * HID) {          // 32,768: fc1_W
            fc1W = (const float*)p;
        } else if (s == HID) {                     // 128: fc1_b
            fc1b = (const float*)p;
        } else if (s == 2L * HID) {                // 256: fc2_W
            fc2W = (const float*)p;
        } else if (s == 2) {                       // 2: fc2_b
            fc2b = (const float*)p;
        }
    }
    cudaFuncSetAttribute(k_gemm, cudaFuncAttributeMaxDynamicSharedMemorySize,
                         GEMM_SMEM);
    k_zero_pool<<<(NGRAPH * HID + 255) / 256, 256>>>();
    run_branch(sc_x, sc_ei, sc_W, sc_b, batch, 0);
    run_branch(fc_x, fc_ei, fc_W, fc_b, batch, 1);
    k_head<<<NGRAPH, 128>>>(fc1W, fc1b);
    k_loss<<<NGRAPH, 256>>>();
    k_final<<<1, 256>>>(fc2W, fc2b, (float*)d_out);
}

// round 3
// speedup vs baseline: 1.1939x; 1.1939x over previous
#include <cuda_runtime.h>
#include <math.h>

#define N_NODESC 100000
#define N_EDGESC 1600000
#define HID 128
#define NGRAPH 256
#define NLAYER 3
#define SCAN_BLOCKS ((N_NODESC + 1023) / 1024)   // 98

// ---------------- scratch (static device globals; no allocation) ----------------
__device__ float g_h[(size_t)N_NODESC * HID];    // GEMM output per layer
__device__ float g_x[(size_t)N_NODESC * HID];    // layer activations
__device__ float g_dis[N_NODESC];                // 1/sqrt(deg)
__device__ int   g_off[N_NODESC + 1];            // CSR offsets (by dst)
__device__ int   g_cur[N_NODESC];                // bucket cursors
__device__ int2  g_ew[N_EDGESC];                 // bucketed {src, enorm-as-int}
__device__ int   g_bsum[SCAN_BLOCKS + 1];
__device__ float g_scg[NGRAPH * HID];
__device__ float g_fcg[NGRAPH * HID];
__device__ float g_z[NGRAPH * HID];
__device__ float g_scn[NGRAPH * HID];
__device__ float g_fcn[NGRAPH * HID];
__device__ float g_loss[2 * NGRAPH];

// ---------------- CSR build ----------------
__global__ void k_zero_counts() {
    int i = blockIdx.x * blockDim.x + threadIdx.x;
    if (i <= N_NODESC) g_off[i] = 0;
}

__global__ void k_hist(const int* __restrict__ dst) {
    for (int e = blockIdx.x * blockDim.x + threadIdx.x; e < N_EDGESC;
         e += gridDim.x * blockDim.x)
        atomicAdd(&g_off[dst[e]], 1);
}

// phase 1: per-block (1024) exclusive scan of counts; also computes g_dis.
__global__ void k_scan1() {
    __shared__ int ws[32];
    int t = threadIdx.x;
    int lane = t & 31, w = t >> 5;
    int idx = blockIdx.x * 1024 + t;
    int v = (idx < N_NODESC) ? g_off[idx] : 0;
    if (idx < N_NODESC) g_dis[idx] = rsqrtf((float)v + 1.0f);
    int x = v;
#pragma unroll
    for (int off = 1; off < 32; off <<= 1) {
        int n = __shfl_up_sync(0xffffffffu, x, off);
        if (lane >= off) x += n;
    }
    if (lane == 31) ws[w] = x;
    __syncthreads();
    if (w == 0) {
        int y = ws[lane];
#pragma unroll
        for (int off = 1; off < 32; off <<= 1) {
            int n = __shfl_up_sync(0xffffffffu, y, off);
            if (lane >= off) y += n;
        }
        ws[lane] = y;
    }
    __syncthreads();
    int inc = x + ((w > 0) ? ws[w - 1] : 0);
    if (idx < N_NODESC) g_off[idx] = inc - v;          // chunk-local exclusive
    if (t == 1023) g_bsum[blockIdx.x] = inc;           // chunk total
}

// phase 2: scan the 98 block sums (single thread; trivial).
__global__ void k_scan2() {
    if (threadIdx.x == 0) {
        int run = 0;
        for (int b = 0; b < SCAN_BLOCKS; ++b) {
            int tmp = g_bsum[b];
            g_bsum[b] = run;
            run += tmp;
        }
        g_off[N_NODESC] = N_EDGESC;
    }
}

// phase 3: add block prefix, init cursors.
__global__ void k_scan3() {
    int idx = blockIdx.x * 1024 + threadIdx.x;
    if (idx < N_NODESC) {
        int o = g_off[idx] + g_bsum[idx >> 10];
        g_off[idx] = o;
        g_cur[idx] = o;
    }
}

__global__ void k_bucket(const int* __restrict__ src, const int* __restrict__ dst) {
    for (int e = blockIdx.x * blockDim.x + threadIdx.x; e < N_EDGESC;
         e += gridDim.x * blockDim.x) {
        int d = dst[e];
        int s = src[e];
        int slot = atomicAdd(&g_cur[d], 1);
        float w = g_dis[s] * g_dis[d];
        g_ew[slot] = make_int2(s, __float_as_int(w));
    }
}

// ---------------- GEMM: H = X @ W   (X [nrows,128], W [128,128]) ----------------
// 64-row x 128-col tile, 256 threads, 4x8 microtile, Xs stored k-major.
#define XS_PITCH 68   // 64 + 4 pad (words)
#define GEMM_SMEM ((128 * XS_PITCH + 128 * 128) * 4)
__global__ void __launch_bounds__(256, 2)
k_gemm(const float* __restrict__ Xext, int use_internal,
       const float* __restrict__ W, int nrows) {
    extern __shared__ float sm[];
    float* Xs = sm;                    // [k=128][XS_PITCH]  (k-major)
    float* Ws = sm + 128 * XS_PITCH;   // [128][128]
    const float* X = use_internal ? (const float*)g_x : Xext;
    int tid = threadIdx.x;
    int r0 = blockIdx.x * 64;
    for (int i = tid; i < 4096; i += 256)
        ((float4*)Ws)[i] = ((const float4*)W)[i];
    // load 64 rows of X, transpose into k-major Xs
    for (int i = tid; i < 2048; i += 256) {
        int row = i >> 5;          // 0..63
        int q = i & 31;            // float4 index -> cols 4q..4q+3
        float4 v;
        if (r0 + row < nrows) v = ((const float4*)(X + (size_t)(r0 + row) * HID))[q];
        else v = make_float4(0.f, 0.f, 0.f, 0.f);
        Xs[(4 * q + 0) * XS_PITCH + row] = v.x;
        Xs[(4 * q + 1) * XS_PITCH + row] = v.y;
        Xs[(4 * q + 2) * XS_PITCH + row] = v.z;
        Xs[(4 * q + 3) * XS_PITCH + row] = v.w;
    }
    __syncthreads();
    int tx = tid & 15, ty = tid >> 4;  // tx: col group, ty: row group
    float acc[4][8];
#pragma unroll
    for (int i = 0; i < 4; i++)
#pragma unroll
        for (int j = 0; j < 8; j++) acc[i][j] = 0.f;
    const float4* Ws4 = (const float4*)Ws;
#pragma unroll 4
    for (int k = 0; k < 128; ++k) {
        float4 av = *(const float4*)(Xs + k * XS_PITCH + ty * 4);
        float4 b0 = Ws4[k * 32 + tx];
        float4 b1 = Ws4[k * 32 + 16 + tx];
        float a[4] = {av.x, av.y, av.z, av.w};
        float bb[8] = {b0.x, b0.y, b0.z, b0.w, b1.x, b1.y, b1.z, b1.w};
#pragma unroll
        for (int i = 0; i < 4; i++)
#pragma unroll
            for (int j = 0; j < 8; j++) acc[i][j] = fmaf(a[i], bb[j], acc[i][j]);
    }
#pragma unroll
    for (int i = 0; i < 4; i++) {
        int row = r0 + ty * 4 + i;
        if (row < nrows) {
            *(float4*)(g_h + (size_t)row * HID + tx * 4) =
                make_float4(acc[i][0], acc[i][1], acc[i][2], acc[i][3]);
            *(float4*)(g_h + (size_t)row * HID + 64 + tx * 4) =
                make_float4(acc[i][4], acc[i][5], acc[i][6], acc[i][7]);
        }
    }
}

// ---------------- fused aggregation: x = relu(segsum + self + bias) ----------------
// one warp per node; lanes own 4 contiguous cols (float4). No atomics.
__global__ void __launch_bounds__(256)
k_agg(const float* __restrict__ bias) {
    int node = (blockIdx.x * blockDim.x + threadIdx.x) >> 5;
    int lane = threadIdx.x & 31;
    if (node >= N_NODESC) return;
    float dd = g_dis[node];
    int beg = g_off[node], end = g_off[node + 1];
    float ax = 0.f, ay = 0.f, az = 0.f, aw = 0.f;
    int e = beg;
    for (; e + 1 < end; e += 2) {
        int2 p0 = g_ew[e];
        int2 p1 = g_ew[e + 1];
        float w0 = __int_as_float(p0.y);
        float w1 = __int_as_float(p1.y);
        float4 h0 = *(const float4*)(g_h + (size_t)p0.x * HID + lane * 4);
        float4 h1 = *(const float4*)(g_h + (size_t)p1.x * HID + lane * 4);
        ax = fmaf(h0.x, w0, ax); ay = fmaf(h0.y, w0, ay);
        az = fmaf(h0.z, w0, az); aw = fmaf(h0.w, w0, aw);
        ax = fmaf(h1.x, w1, ax); ay = fmaf(h1.y, w1, ay);
        az = fmaf(h1.z, w1, az); aw = fmaf(h1.w, w1, aw);
    }
    if (e < end) {
        int2 p0 = g_ew[e];
        float w0 = __int_as_float(p0.y);
        float4 h0 = *(const float4*)(g_h + (size_t)p0.x * HID + lane * 4);
        ax = fmaf(h0.x, w0, ax); ay = fmaf(h0.y, w0, ay);
        az = fmaf(h0.z, w0, az); aw = fmaf(h0.w, w0, aw);
    }
    float4 hd = *(const float4*)(g_h + (size_t)node * HID + lane * 4);
    float sn = dd * dd;
    float4 bb = *(const float4*)(bias + lane * 4);
    ax = fmaxf(fmaf(hd.x, sn, ax) + bb.x, 0.f);
    ay = fmaxf(fmaf(hd.y, sn, ay) + bb.y, 0.f);
    az = fmaxf(fmaf(hd.z, sn, az) + bb.z, 0.f);
    aw = fmaxf(fmaf(hd.w, sn, aw) + bb.w, 0.f);
    *(float4*)(g_x + (size_t)node * HID + lane * 4) = make_float4(ax, ay, az, aw);
}

// ---------------- pooling: block per graph, binary-searched bounds ----------------
__global__ void __launch_bounds__(128)
k_pool2(const int* __restrict__ batch, int which) {
    int g = blockIdx.x, t = threadIdx.x;  // 128 threads
    __shared__ int s_lo, s_hi;
    if (t == 0) {
        int lo = 0, hi = N_NODESC;
        while (lo < hi) { int m = (lo + hi) >> 1; if (batch[m] < g) lo = m + 1; else hi = m; }
        s_lo = lo;
    }
    if (t == 32) {
        int lo = 0, hi = N_NODESC;
        while (lo < hi) { int m = (lo + hi) >> 1; if (batch[m] < g + 1) lo = m + 1; else hi = m; }
        s_hi = lo;
    }
    __syncthreads();
    int lo = s_lo, hi = s_hi;
    float acc = 0.f;
    int n = lo;
    for (; n + 3 < hi; n += 4) {
        float v0 = g_x[(size_t)n * HID + t];
        float v1 = g_x[(size_t)(n + 1) * HID + t];
        float v2 = g_x[(size_t)(n + 2) * HID + t];
        float v3 = g_x[(size_t)(n + 3) * HID + t];
        acc += (v0 + v1) + (v2 + v3);
    }
    for (; n < hi; ++n) acc += g_x[(size_t)n * HID + t];
    (which ? g_fcg : g_scg)[g * HID + t] = acc;
}

// ---------------- head: z = relu(concat(g)@fc1+b); normalize g ----------------
__global__ void k_head(const float* __restrict__ fc1W, const float* __restrict__ fc1b) {
    int b = blockIdx.x, t = threadIdx.x;  // 128 threads
    __shared__ float s[256];
    __shared__ float red[128];
    __shared__ float inv_ns, inv_nf;
    s[t] = g_scg[b * HID + t];
    s[128 + t] = g_fcg[b * HID + t];
    __syncthreads();
    red[t] = s[t] * s[t];
    __syncthreads();
    for (int off = 64; off > 0; off >>= 1) {
        if (t < off) red[t] += red[t + off];
        __syncthreads();
    }
    if (t == 0) inv_ns = 1.0f / fmaxf(sqrtf(red[0]), 1e-12f);
    __syncthreads();
    red[t] = s[128 + t] * s[128 + t];
    __syncthreads();
    for (int off = 64; off > 0; off >>= 1) {
        if (t < off) red[t] += red[t + off];
        __syncthreads();
    }
    if (t == 0) inv_nf = 1.0f / fmaxf(sqrtf(red[0]), 1e-12f);
    __syncthreads();
    float acc = 0.f;
#pragma unroll 8
    for (int k = 0; k < 256; k++) acc = fmaf(s[k], fc1W[k * HID + t], acc);
    acc += fc1b[t];
    g_z[b * HID + t] = fmaxf(acc, 0.f);
    g_scn[b * HID + t] = s[t] * inv_ns;
    g_fcn[b * HID + t] = s[128 + t] * inv_nf;
}

// ---------------- contrastive row losses ----------------
__global__ void k_loss() {
    int i = blockIdx.x, j = threadIdx.x;  // 256 threads
    __shared__ float sni[HID], fni[HID];
    __shared__ float red[256];
    __shared__ float diag_sc, diag_fc, Msc, Mfc, Ssc, Sfc;
    if (j < HID) { sni[j] = g_scn[i * HID + j]; fni[j] = g_fcn[i * HID + j]; }
    __syncthreads();
    float dsf = 0.f, dss = 0.f, dfs = 0.f, dff = 0.f;
    const float* srow = &g_scn[j * HID];
    const float* frow = &g_fcn[j * HID];
#pragma unroll 4
    for (int k = 0; k < HID; k++) {
        float sj = srow[k], fj = frow[k], si = sni[k], fi = fni[k];
        dsf = fmaf(si, fj, dsf);
        dss = fmaf(si, sj, dss);
        dfs = fmaf(fi, sj, dfs);
        dff = fmaf(fi, fj, dff);
    }
    const float tt = 2.0f;          // 1/TEMPERATURE
    float e1 = dsf * tt;
    float e2 = (j == i) ? 0.f : 0.8f * tt * dss;
    float f1 = dfs * tt;
    float f2 = (j == i) ? 0.f : 0.8f * tt * dff;
    if (j == i) { diag_sc = e1; diag_fc = f1; }
    red[j] = fmaxf(e1, e2);
    __syncthreads();
    for (int off = 128; off > 0; off >>= 1) {
        if (j < off) red[j] = fmaxf(red[j], red[j + off]);
        __syncthreads();
    }
    if (j == 0) Msc = red[0];
    __syncthreads();
    red[j] = expf(e1 - Msc) + expf(e2 - Msc);
    __syncthreads();
    for (int off = 128; off > 0; off >>= 1) {
        if (j < off) red[j] += red[j + off];
        __syncthreads();
    }
    if (j == 0) Ssc = red[0];
    __syncthreads();
    red[j] = fmaxf(f1, f2);
    __syncthreads();
    for (int off = 128; off > 0; off >>= 1) {
        if (j < off) red[j] = fmaxf(red[j], red[j + off]);
        __syncthreads();
    }
    if (j == 0) Mfc = red[0];
    __syncthreads();
    red[j] = expf(f1 - Mfc) + expf(f2 - Mfc);
    __syncthreads();
    for (int off = 128; off > 0; off >>= 1) {
        if (j < off) red[j] += red[j + off];
        __syncthreads();
    }
    if (j == 0) {
        Sfc = red[0];
        g_loss[i] = (Msc + logf(Ssc)) - diag_sc;
        g_loss[NGRAPH + i] = (Mfc + logf(Sfc)) - diag_fc;
    }
}

// ---------------- final: classifier logits + log_softmax + scalar ----------------
__global__ void k_final(const float* __restrict__ fc2W, const float* __restrict__ fc2b,
                        float* __restrict__ out) {
    __shared__ float red[256];
    __shared__ float scalar;
    int t = threadIdx.x;
    red[t] = g_loss[t] + g_loss[NGRAPH + t];
    __syncthreads();
    for (int off = 128; off > 0; off >>= 1) {
        if (t < off) red[t] += red[t + off];
        __syncthreads();
    }
    if (t == 0) scalar = red[0] / (2.0f * NGRAPH);
    __syncthreads();
    float l0 = fc2b[0], l1 = fc2b[1];
    const float* z = &g_z[t * HID];
#pragma unroll 4
    for (int k = 0; k < HID; k++) {
        float zv = z[k];
        l0 = fmaf(zv, fc2W[2 * k], l0);
        l1 = fmaf(zv, fc2W[2 * k + 1], l1);
    }
    float m = fmaxf(l0, l1);
    float lse = m + logf(expf(l0 - m) + expf(l1 - m));
    out[2 * t] = l0 - lse + scalar;
    out[2 * t + 1] = l1 - lse + scalar;
}

// ---------------- host side ----------------
static void run_branch(const float* x_in, const int* ei, const float* W,
                       const float* b, const int* batch, int which) {
    const int* src = ei;
    const int* dst = ei + N_EDGESC;
    k_zero_counts<<<(N_NODESC + 256) / 256, 256>>>();
    k_hist<<<2048, 256>>>(dst);
    k_scan1<<<SCAN_BLOCKS, 1024>>>();
    k_scan2<<<1, 32>>>();
    k_scan3<<<SCAN_BLOCKS, 1024>>>();
    k_bucket<<<2048, 256>>>(src, dst);
    for (int l = 0; l < NLAYER; ++l) {
        k_gemm<<<(N_NODESC + 63) / 64, 256, GEMM_SMEM>>>(
            x_in, l > 0 ? 1 : 0, W + (size_t)l * HID * HID, N_NODESC);
        k_agg<<<(N_NODESC * 32 + 255) / 256, 256>>>(b + (size_t)l * HID);
    }
    k_pool2<<<NGRAPH, 128>>>(batch, which);
}

extern "C" void kernel_launch(void* const* d_in, const int* in_sizes, int n_in,
                              void* d_out, int out_size) {
    const float *sc_x = 0, *fc_x = 0, *sc_W = 0, *sc_b = 0, *fc_W = 0, *fc_b = 0;
    const float *fc1W = 0, *fc1b = 0, *fc2W = 0, *fc2b = 0;
    const int *sc_ei = 0, *fc_ei = 0, *batch = 0;
    for (int i = 0; i < n_in; i++) {
        long s = in_sizes[i];
        const void* p = d_in[i];
        if (s == (long)N_NODESC * HID) {
            if (!sc_x) sc_x = (const float*)p; else fc_x = (const float*)p;
        } else if (s == 2L * N_EDGESC) {
            if (!sc_ei) sc_ei = (const int*)p; else fc_ei = (const int*)p;
        } else if (s == N_NODESC) {
            batch = (const int*)p;
        } else if (s == (long)NLAYER * HID * HID) {
            if (!sc_W) sc_W = (const float*)p; else fc_W = (const float*)p;
        } else if (s == (long)NLAYER * HID) {
            if (!sc_b) sc_b = (const float*)p; else fc_b = (const float*)p;
        } else if (s == 2L * HID * HID) {
            fc1W = (const float*)p;
        } else if (s == HID) {
            fc1b = (const float*)p;
        } else if (s == 2L * HID) {
            fc2W = (const float*)p;
        } else if (s == 2) {
            fc2b = (const float*)p;
        }
    }
    cudaFuncSetAttribute(k_gemm, cudaFuncAttributeMaxDynamicSharedMemorySize,
                         GEMM_SMEM);
    run_branch(sc_x, sc_ei, sc_W, sc_b, batch, 0);
    run_branch(fc_x, fc_ei, fc_W, fc_b, batch, 1);
    k_head<<<NGRAPH, 128>>>(fc1W, fc1b);
    k_loss<<<NGRAPH, 256>>>();
    k_final<<<1, 256>>>(fc2W, fc2b, (float*)d_out);
}

// round 5
// speedup vs baseline: 1.2465x; 1.0440x over previous
#include <cuda_runtime.h>
#include <cuda_bf16.h>
#include <math.h>
#include <stdint.h>

#define N_NODESC 100000
#define N_EDGESC 1600000
#define HID 128
#define NGRAPH 256
#define NLAYER 3
#define SCAN_BLOCKS ((N_NODESC + 1023) / 1024)   // 98
#define NTILES ((N_NODESC + 127) / 128)          // 782

// ---------------- scratch (static device globals; no allocation) ----------------
__device__ float g_h[(size_t)N_NODESC * HID];    // GEMM output per layer
__device__ float g_x[(size_t)N_NODESC * HID];    // layer activations
__device__ float g_dis[N_NODESC];                // 1/sqrt(deg)
__device__ int   g_off[N_NODESC + 1];            // CSR offsets (by dst)
__device__ int   g_cur[N_NODESC];                // bucket cursors
__device__ int2  g_ew[N_EDGESC];                 // bucketed {src, enorm-as-int}
__device__ int   g_bsum[SCAN_BLOCKS + 1];
__device__ float g_scg[NGRAPH * HID];
__device__ float g_fcg[NGRAPH * HID];
__device__ float g_z[NGRAPH * HID];
__device__ float g_scn[NGRAPH * HID];
__device__ float g_fcn[NGRAPH * HID];
__device__ float g_loss[2 * NGRAPH];

// ---------------- helpers ----------------
__device__ __forceinline__ uint32_t smem_u32(const void* p) {
    uint32_t a;
    asm("{ .reg .u64 t; cvta.to.shared.u64 t, %1; cvt.u32.u64 %0, t; }"
        : "=r"(a) : "l"(p));
    return a;
}
__device__ __forceinline__ uint32_t pack_hi2(float a, float b, float* la, float* lb) {
    __nv_bfloat16 ha = __float2bfloat16_rn(a);
    __nv_bfloat16 hb = __float2bfloat16_rn(b);
    *la = a - __bfloat162float(ha);
    *lb = b - __bfloat162float(hb);
    return ((uint32_t)__bfloat16_as_ushort(hb) << 16) | (uint32_t)__bfloat16_as_ushort(ha);
}
__device__ __forceinline__ uint32_t pack_lo2(float la, float lb) {
    return ((uint32_t)__bfloat16_as_ushort(__float2bfloat16_rn(lb)) << 16) |
           (uint32_t)__bfloat16_as_ushort(__float2bfloat16_rn(la));
}
#define LDSM_X4(r0, r1, r2, r3, addr) \
    asm volatile("ldmatrix.sync.aligned.m8n8.x4.shared.b16 {%0,%1,%2,%3}, [%4];" \
                 : "=r"(r0), "=r"(r1), "=r"(r2), "=r"(r3) : "r"(addr))
#define LDSM_X4T(r0, r1, r2, r3, addr) \
    asm volatile("ldmatrix.sync.aligned.m8n8.x4.trans.shared.b16 {%0,%1,%2,%3}, [%4];" \
                 : "=r"(r0), "=r"(r1), "=r"(r2), "=r"(r3) : "r"(addr))
#define MMA16816(c, a, b0, b1) \
    asm volatile("mma.sync.aligned.m16n8k16.row.col.f32.bf16.bf16.f32 " \
                 "{%0,%1,%2,%3}, {%4,%5,%6,%7}, {%8,%9}, {%0,%1,%2,%3};" \
                 : "+f"((c)[0]), "+f"((c)[1]), "+f"((c)[2]), "+f"((c)[3]) \
                 : "r"((a)[0]), "r"((a)[1]), "r"((a)[2]), "r"((a)[3]), \
                   "r"(b0), "r"(b1))

// ---------------- CSR build ----------------
__global__ void k_zero_counts() {
    int i = blockIdx.x * blockDim.x + threadIdx.x;
    if (i <= N_NODESC) g_off[i] = 0;
}

__global__ void k_hist(const int* __restrict__ dst) {
    for (int e = blockIdx.x * blockDim.x + threadIdx.x; e < N_EDGESC;
         e += gridDim.x * blockDim.x)
        atomicAdd(&g_off[dst[e]], 1);
}

__global__ void k_scan1() {
    __shared__ int ws[32];
    int t = threadIdx.x;
    int lane = t & 31, w = t >> 5;
    int idx = blockIdx.x * 1024 + t;
    int v = (idx < N_NODESC) ? g_off[idx] : 0;
    if (idx < N_NODESC) g_dis[idx] = rsqrtf((float)v + 1.0f);
    int x = v;
#pragma unroll
    for (int off = 1; off < 32; off <<= 1) {
        int n = __shfl_up_sync(0xffffffffu, x, off);
        if (lane >= off) x += n;
    }
    if (lane == 31) ws[w] = x;
    __syncthreads();
    if (w == 0) {
        int y = ws[lane];
#pragma unroll
        for (int off = 1; off < 32; off <<= 1) {
            int n = __shfl_up_sync(0xffffffffu, y, off);
            if (lane >= off) y += n;
        }
        ws[lane] = y;
    }
    __syncthreads();
    int inc = x + ((w > 0) ? ws[w - 1] : 0);
    if (idx < N_NODESC) g_off[idx] = inc - v;
    if (t == 1023) g_bsum[blockIdx.x] = inc;
}

__global__ void k_scan2() {
    if (threadIdx.x == 0) {
        int run = 0;
        for (int b = 0; b < SCAN_BLOCKS; ++b) {
            int tmp = g_bsum[b];
            g_bsum[b] = run;
            run += tmp;
        }
        g_off[N_NODESC] = N_EDGESC;
    }
}

__global__ void k_scan3() {
    int idx = blockIdx.x * 1024 + threadIdx.x;
    if (idx < N_NODESC) {
        int o = g_off[idx] + g_bsum[idx >> 10];
        g_off[idx] = o;
        g_cur[idx] = o;
    }
}

__global__ void k_bucket(const int* __restrict__ src, const int* __restrict__ dst) {
    for (int e = blockIdx.x * blockDim.x + threadIdx.x; e < N_EDGESC;
         e += gridDim.x * blockDim.x) {
        int d = dst[e];
        int s = src[e];
        int slot = atomicAdd(&g_cur[d], 1);
        float w = g_dis[s] * g_dis[d];
        g_ew[slot] = make_int2(s, __float_as_int(w));
    }
}

// ---------------- tensor-core GEMM via mma.sync: H = X @ W, bf16 3-term split ----
// SMEM: Ahi/Alo: [128 rows][136] bf16 (row = node row, col = k).
//       Bhi/Blo: [128 k][136] bf16 (row = k, col = n).  pitch 136 el = 272 B
#define APITCH 136
#define TILE_B (128 * APITCH * 2)      // 34816 bytes
#define OFF_AHI 0
#define OFF_ALO TILE_B
#define OFF_BHI (2 * TILE_B)
#define OFF_BLO (3 * TILE_B)
#define GEMM_SMEM (4 * TILE_B)         // 139264

__global__ void __launch_bounds__(256, 1)
k_gemm_mma(const float* __restrict__ Xext, int use_internal,
           const float* __restrict__ W, int nrows) {
    extern __shared__ char sm[];
    uint32_t base = smem_u32(sm);
    const float* X = use_internal ? (const float*)g_x : Xext;
    int tid = threadIdx.x;
    int r0 = blockIdx.x * 128;

    // ---- convert W -> Bhi/Blo (B[k][n], W already [k][n] row-major) ----
    for (int g = tid; g < 128 * 32; g += 256) {
        int k = g >> 5, q = g & 31;          // q: float4 group along n
        float4 v = *(const float4*)(W + (size_t)k * HID + q * 4);
        float l0, l1, l2, l3;
        uint32_t h01 = pack_hi2(v.x, v.y, &l0, &l1);
        uint32_t h23 = pack_hi2(v.z, v.w, &l2, &l3);
        uint32_t off = (uint32_t)(k * APITCH + q * 4) * 2u;
        *(uint2*)(sm + OFF_BHI + off) = make_uint2(h01, h23);
        *(uint2*)(sm + OFF_BLO + off) = make_uint2(pack_lo2(l0, l1), pack_lo2(l2, l3));
    }
    // ---- convert X tile -> Ahi/Alo ----
    for (int g = tid; g < 128 * 32; g += 256) {
        int row = g >> 5, q = g & 31;
        int grow = r0 + row;
        float4 v = (grow < nrows)
            ? *(const float4*)(X + (size_t)grow * HID + q * 4)
            : make_float4(0.f, 0.f, 0.f, 0.f);
        float l0, l1, l2, l3;
        uint32_t h01 = pack_hi2(v.x, v.y, &l0, &l1);
        uint32_t h23 = pack_hi2(v.z, v.w, &l2, &l3);
        uint32_t off = (uint32_t)(row * APITCH + q * 4) * 2u;
        *(uint2*)(sm + OFF_AHI + off) = make_uint2(h01, h23);
        *(uint2*)(sm + OFF_ALO + off) = make_uint2(pack_lo2(l0, l1), pack_lo2(l2, l3));
    }
    __syncthreads();

    int w = tid >> 5, lane = tid & 31;
    int wm = w & 3, wn = w >> 2;            // 4 row-groups x 2 col-groups
    int rbase = wm * 32, cbase = wn * 64;

    float acc[2][8][4];
#pragma unroll
    for (int m = 0; m < 2; m++)
#pragma unroll
        for (int n = 0; n < 8; n++)
#pragma unroll
            for (int c = 0; c < 4; c++) acc[m][n][c] = 0.f;

    // A ldmatrix address pieces: row = rbase + m*16 + (lane&15), colhalf = (lane>>4)*8
    int a_r = lane & 15, a_c = (lane >> 4) * 8;
    // B ldmatrix (trans): row(k) = k0 + ((lane>>3)&1)*8 + (lane&7), col = n0 + (lane>>4)*8
    int b_kr = ((lane >> 3) & 1) * 8 + (lane & 7), b_c = (lane >> 4) * 8;

#pragma unroll
    for (int ks = 0; ks < 8; ++ks) {
        int k0 = ks * 16;
        uint32_t ahi[2][4], alo[2][4];
#pragma unroll
        for (int m = 0; m < 2; ++m) {
            uint32_t aoff = (uint32_t)((rbase + m * 16 + a_r) * APITCH + k0 + a_c) * 2u;
            LDSM_X4(ahi[m][0], ahi[m][1], ahi[m][2], ahi[m][3], base + OFF_AHI + aoff);
            LDSM_X4(alo[m][0], alo[m][1], alo[m][2], alo[m][3], base + OFF_ALO + aoff);
        }
#pragma unroll
        for (int n2 = 0; n2 < 4; ++n2) {
            int n0 = cbase + n2 * 16;
            uint32_t boff = (uint32_t)((k0 + b_kr) * APITCH + n0 + b_c) * 2u;
            uint32_t bh0, bh1, bh2, bh3, bl0, bl1, bl2, bl3;
            LDSM_X4T(bh0, bh1, bh2, bh3, base + OFF_BHI + boff);
            LDSM_X4T(bl0, bl1, bl2, bl3, base + OFF_BLO + boff);
#pragma unroll
            for (int m = 0; m < 2; ++m) {
                MMA16816(acc[m][n2 * 2], ahi[m], bh0, bh1);
                MMA16816(acc[m][n2 * 2 + 1], ahi[m], bh2, bh3);
                MMA16816(acc[m][n2 * 2], ahi[m], bl0, bl1);
                MMA16816(acc[m][n2 * 2 + 1], ahi[m], bl2, bl3);
                MMA16816(acc[m][n2 * 2], alo[m], bh0, bh1);
                MMA16816(acc[m][n2 * 2 + 1], alo[m], bh2, bh3);
            }
        }
    }

    // ---- epilogue: c0,c1 -> row (lane>>2), cols 2*(lane&3); c2,c3 -> row+8 ----
#pragma unroll
    for (int m = 0; m < 2; ++m) {
        int rA = r0 + rbase + m * 16 + (lane >> 2);
        int rB = rA + 8;
#pragma unroll
        for (int ng = 0; ng < 8; ++ng) {
            int col = cbase + ng * 8 + (lane & 3) * 2;
            if (rA < nrows)
                *(float2*)(g_h + (size_t)rA * HID + col) =
                    make_float2(acc[m][ng][0], acc[m][ng][1]);
            if (rB < nrows)
                *(float2*)(g_h + (size_t)rB * HID + col) =
                    make_float2(acc[m][ng][2], acc[m][ng][3]);
        }
    }
}

// ---------------- fused aggregation: x = relu(segsum + self + bias) ----------------
__global__ void __launch_bounds__(256)
k_agg(const float* __restrict__ bias) {
    int node = (blockIdx.x * blockDim.x + threadIdx.x) >> 5;
    int lane = threadIdx.x & 31;
    if (node >= N_NODESC) return;
    float dd = g_dis[node];
    int beg = g_off[node], end = g_off[node + 1];
    float ax = 0.f, ay = 0.f, az = 0.f, aw = 0.f;
    int e = beg;
    for (; e + 1 < end; e += 2) {
        int2 p0 = g_ew[e];
        int2 p1 = g_ew[e + 1];
        float w0 = __int_as_float(p0.y);
        float w1 = __int_as_float(p1.y);
        float4 h0 = *(const float4*)(g_h + (size_t)p0.x * HID + lane * 4);
        float4 h1 = *(const float4*)(g_h + (size_t)p1.x * HID + lane * 4);
        ax = fmaf(h0.x, w0, ax); ay = fmaf(h0.y, w0, ay);
        az = fmaf(h0.z, w0, az); aw = fmaf(h0.w, w0, aw);
        ax = fmaf(h1.x, w1, ax); ay = fmaf(h1.y, w1, ay);
        az = fmaf(h1.z, w1, az); aw = fmaf(h1.w, w1, aw);
    }
    if (e < end) {
        int2 p0 = g_ew[e];
        float w0 = __int_as_float(p0.y);
        float4 h0 = *(const float4*)(g_h + (size_t)p0.x * HID + lane * 4);
        ax = fmaf(h0.x, w0, ax); ay = fmaf(h0.y, w0, ay);
        az = fmaf(h0.z, w0, az); aw = fmaf(h0.w, w0, aw);
    }
    float4 hd = *(const float4*)(g_h + (size_t)node * HID + lane * 4);
    float sn = dd * dd;
    float4 bb = *(const float4*)(bias + lane * 4);
    ax = fmaxf(fmaf(hd.x, sn, ax) + bb.x, 0.f);
    ay = fmaxf(fmaf(hd.y, sn, ay) + bb.y, 0.f);
    az = fmaxf(fmaf(hd.z, sn, az) + bb.z, 0.f);
    aw = fmaxf(fmaf(hd.w, sn, aw) + bb.w, 0.f);
    *(float4*)(g_x + (size_t)node * HID + lane * 4) = make_float4(ax, ay, az, aw);
}

// ---------------- pooling: block per graph, binary-searched bounds ----------------
__global__ void __launch_bounds__(128)
k_pool2(const int* __restrict__ batch, int which) {
    int g = blockIdx.x, t = threadIdx.x;
    __shared__ int s_lo, s_hi;
    if (t == 0) {
        int lo = 0, hi = N_NODESC;
        while (lo < hi) { int m = (lo + hi) >> 1; if (batch[m] < g) lo = m + 1; else hi = m; }
        s_lo = lo;
    }
    if (t == 32) {
        int lo = 0, hi = N_NODESC;
        while (lo < hi) { int m = (lo + hi) >> 1; if (batch[m] < g + 1) lo = m + 1; else hi = m; }
        s_hi = lo;
    }
    __syncthreads();
    int lo = s_lo, hi = s_hi;
    float acc = 0.f;
    int n = lo;
    for (; n + 3 < hi; n += 4) {
        float v0 = g_x[(size_t)n * HID + t];
        float v1 = g_x[(size_t)(n + 1) * HID + t];
        float v2 = g_x[(size_t)(n + 2) * HID + t];
        float v3 = g_x[(size_t)(n + 3) * HID + t];
        acc += (v0 + v1) + (v2 + v3);
    }
    for (; n < hi; ++n) acc += g_x[(size_t)n * HID + t];
    (which ? g_fcg : g_scg)[g * HID + t] = acc;
}

// ---------------- head ----------------
__global__ void k_head(const float* __restrict__ fc1W, const float* __restrict__ fc1b) {
    int b = blockIdx.x, t = threadIdx.x;
    __shared__ float s[256];
    __shared__ float red[128];
    __shared__ float inv_ns, inv_nf;
    s[t] = g_scg[b * HID + t];
    s[128 + t] = g_fcg[b * HID + t];
    __syncthreads();
    red[t] = s[t] * s[t];
    __syncthreads();
    for (int off = 64; off > 0; off >>= 1) {
        if (t < off) red[t] += red[t + off];
        __syncthreads();
    }
    if (t == 0) inv_ns = 1.0f / fmaxf(sqrtf(red[0]), 1e-12f);
    __syncthreads();
    red[t] = s[128 + t] * s[128 + t];
    __syncthreads();
    for (int off = 64; off > 0; off >>= 1) {
        if (t < off) red[t] += red[t + off];
        __syncthreads();
    }
    if (t == 0) inv_nf = 1.0f / fmaxf(sqrtf(red[0]), 1e-12f);
    __syncthreads();
    float acc = 0.f;
#pragma unroll 8
    for (int k = 0; k < 256; k++) acc = fmaf(s[k], fc1W[k * HID + t], acc);
    acc += fc1b[t];
    g_z[b * HID + t] = fmaxf(acc, 0.f);
    g_scn[b * HID + t] = s[t] * inv_ns;
    g_fcn[b * HID + t] = s[128 + t] * inv_nf;
}

// ---------------- contrastive row losses ----------------
__global__ void k_loss() {
    int i = blockIdx.x, j = threadIdx.x;
    __shared__ float sni[HID], fni[HID];
    __shared__ float red[256];
    __shared__ float diag_sc, diag_fc, Msc, Mfc, Ssc, Sfc;
    if (j < HID) { sni[j] = g_scn[i * HID + j]; fni[j] = g_fcn[i * HID + j]; }
    __syncthreads();
    float dsf = 0.f, dss = 0.f, dfs = 0.f, dff = 0.f;
    const float* srow = &g_scn[j * HID];
    const float* frow = &g_fcn[j * HID];
#pragma unroll 4
    for (int k = 0; k < HID; k++) {
        float sj = srow[k], fj = frow[k], si = sni[k], fi = fni[k];
        dsf = fmaf(si, fj, dsf);
        dss = fmaf(si, sj, dss);
        dfs = fmaf(fi, sj, dfs);
        dff = fmaf(fi, fj, dff);
    }
    const float tt = 2.0f;
    float e1 = dsf * tt;
    float e2 = (j == i) ? 0.f : 0.8f * tt * dss;
    float f1 = dfs * tt;
    float f2 = (j == i) ? 0.f : 0.8f * tt * dff;
    if (j == i) { diag_sc = e1; diag_fc = f1; }
    red[j] = fmaxf(e1, e2);
    __syncthreads();
    for (int off = 128; off > 0; off >>= 1) {
        if (j < off) red[j] = fmaxf(red[j], red[j + off]);
        __syncthreads();
    }
    if (j == 0) Msc = red[0];
    __syncthreads();
    red[j] = expf(e1 - Msc) + expf(e2 - Msc);
    __syncthreads();
    for (int off = 128; off > 0; off >>= 1) {
        if (j < off) red[j] += red[j + off];
        __syncthreads();
    }
    if (j == 0) Ssc = red[0];
    __syncthreads();
    red[j] = fmaxf(f1, f2);
    __syncthreads();
    for (int off = 128; off > 0; off >>= 1) {
        if (j < off) red[j] = fmaxf(red[j], red[j + off]);
        __syncthreads();
    }
    if (j == 0) Mfc = red[0];
    __syncthreads();
    red[j] = expf(f1 - Mfc) + expf(f2 - Mfc);
    __syncthreads();
    for (int off = 128; off > 0; off >>= 1) {
        if (j < off) red[j] += red[j + off];
        __syncthreads();
    }
    if (j == 0) {
        Sfc = red[0];
        g_loss[i] = (Msc + logf(Ssc)) - diag_sc;
        g_loss[NGRAPH + i] = (Mfc + logf(Sfc)) - diag_fc;
    }
}

// ---------------- final ----------------
__global__ void k_final(const float* __restrict__ fc2W, const float* __restrict__ fc2b,
                        float* __restrict__ out) {
    __shared__ float red[256];
    __shared__ float scalar;
    int t = threadIdx.x;
    red[t] = g_loss[t] + g_loss[NGRAPH + t];
    __syncthreads();
    for (int off = 128; off > 0; off >>= 1) {
        if (t < off) red[t] += red[t + off];
        __syncthreads();
    }
    if (t == 0) scalar = red[0] / (2.0f * NGRAPH);
    __syncthreads();
    float l0 = fc2b[0], l1 = fc2b[1];
    const float* z = &g_z[t * HID];
#pragma unroll 4
    for (int k = 0; k < HID; k++) {
        float zv = z[k];
        l0 = fmaf(zv, fc2W[2 * k], l0);
        l1 = fmaf(zv, fc2W[2 * k + 1], l1);
    }
    float m = fmaxf(l0, l1);
    float lse = m + logf(expf(l0 - m) + expf(l1 - m));
    out[2 * t] = l0 - lse + scalar;
    out[2 * t + 1] = l1 - lse + scalar;
}

// ---------------- host side ----------------
static void run_branch(const float* x_in, const int* ei, const float* W,
                       const float* b, const int* batch, int which) {
    const int* src = ei;
    const int* dst = ei + N_EDGESC;
    k_zero_counts<<<(N_NODESC + 256) / 256, 256>>>();
    k_hist<<<2048, 256>>>(dst);
    k_scan1<<<SCAN_BLOCKS, 1024>>>();
    k_scan2<<<1, 32>>>();
    k_scan3<<<SCAN_BLOCKS, 1024>>>();
    k_bucket<<<2048, 256>>>(src, dst);
    for (int l = 0; l < NLAYER; ++l) {
        k_gemm_mma<<<NTILES, 256, GEMM_SMEM>>>(
            x_in, l > 0 ? 1 : 0, W + (size_t)l * HID * HID, N_NODESC);
        k_agg<<<(N_NODESC * 32 + 255) / 256, 256>>>(b + (size_t)l * HID);
    }
    k_pool2<<<NGRAPH, 128>>>(batch, which);
}

extern "C" void kernel_launch(void* const* d_in, const int* in_sizes, int n_in,
                              void* d_out, int out_size) {
    const float *sc_x = 0, *fc_x = 0, *sc_W = 0, *sc_b = 0, *fc_W = 0, *fc_b = 0;
    const float *fc1W = 0, *fc1b = 0, *fc2W = 0, *fc2b = 0;
    const int *sc_ei = 0, *fc_ei = 0, *batch = 0;
    for (int i = 0; i < n_in; i++) {
        long s = in_sizes[i];
        const void* p = d_in[i];
        if (s == (long)N_NODESC * HID) {
            if (!sc_x) sc_x = (const float*)p; else fc_x = (const float*)p;
        } else if (s == 2L * N_EDGESC) {
            if (!sc_ei) sc_ei = (const int*)p; else fc_ei = (const int*)p;
        } else if (s == N_NODESC) {
            batch = (const int*)p;
        } else if (s == (long)NLAYER * HID * HID) {
            if (!sc_W) sc_W = (const float*)p; else fc_W = (const float*)p;
        } else if (s == (long)NLAYER * HID) {
            if (!sc_b) sc_b = (const float*)p; else fc_b = (const float*)p;
        } else if (s == 2L * HID * HID) {
            fc1W = (const float*)p;
        } else if (s == HID) {
            fc1b = (const float*)p;
        } else if (s == 2L * HID) {
            fc2W = (const float*)p;
        } else if (s == 2) {
            fc2b = (const float*)p;
        }
    }
    cudaFuncSetAttribute(k_gemm_mma, cudaFuncAttributeMaxDynamicSharedMemorySize,
                         GEMM_SMEM);
    run_branch(sc_x, sc_ei, sc_W, sc_b, batch, 0);
    run_branch(fc_x, fc_ei, fc_W, fc_b, batch, 1);
    k_head<<<NGRAPH, 128>>>(fc1W, fc1b);
    k_loss<<<NGRAPH, 256>>>();
    k_final<<<1, 256>>>(fc2W, fc2b, (float*)d_out);
}

// round 6
// speedup vs baseline: 1.5444x; 1.2390x over previous
#include <cuda_runtime.h>
#include <cuda_bf16.h>
#include <cuda_fp16.h>
#include <math.h>
#include <stdint.h>

#define N_NODESC 100000
#define N_EDGESC 1600000
#define HID 128
#define NGRAPH 256
#define NLAYER 3
#define SCAN_BLOCKS ((N_NODESC + 1023) / 1024)   // 98
#define NTILES ((N_NODESC + 127) / 128)          // 782

// ---------------- scratch (static device globals; no allocation) ----------------
__device__ __half    g_h[2][(size_t)N_NODESC * HID];   // GEMM output (fp16)
__device__ uint32_t  g_xs[2][(size_t)N_NODESC * HID];  // activations, packed bf16 hi|lo
__device__ uint32_t  g_ws[2][NLAYER * HID * HID];      // W, packed bf16 hi|lo
__device__ float     g_dis[2][N_NODESC];
__device__ int       g_off[2][N_NODESC + 1];
__device__ int       g_cur[2][N_NODESC];
__device__ int2      g_ew[2][N_EDGESC];                // {src, enorm}
__device__ int       g_bsum[2][SCAN_BLOCKS + 1];
__device__ float     g_scg[NGRAPH * HID];
__device__ float     g_fcg[NGRAPH * HID];
__device__ float     g_z[NGRAPH * HID];
__device__ float     g_scn[NGRAPH * HID];
__device__ float     g_fcn[NGRAPH * HID];
__device__ float     g_loss[2 * NGRAPH];

// ---------------- helpers ----------------
__device__ __forceinline__ uint32_t smem_u32(const void* p) {
    uint32_t a;
    asm("{ .reg .u64 t; cvta.to.shared.u64 t, %1; cvt.u32.u64 %0, t; }"
        : "=r"(a) : "l"(p));
    return a;
}
// pack fp32 -> (bf16 hi in low16) | (bf16 lo residual in high16)
__device__ __forceinline__ uint32_t packsplit(float v) {
    __nv_bfloat16 h = __float2bfloat16_rn(v);
    float lo = v - __bfloat162float(h);
    __nv_bfloat16 l = __float2bfloat16_rn(lo);
    return (uint32_t)__bfloat16_as_ushort(h) |
           ((uint32_t)__bfloat16_as_ushort(l) << 16);
}
__device__ __forceinline__ float unpacksplit(uint32_t p) {
    return __bfloat162float(__ushort_as_bfloat16((unsigned short)(p & 0xffffu))) +
           __bfloat162float(__ushort_as_bfloat16((unsigned short)(p >> 16)));
}
#define LDSM_X4(r0, r1, r2, r3, addr) \
    asm volatile("ldmatrix.sync.aligned.m8n8.x4.shared.b16 {%0,%1,%2,%3}, [%4];" \
                 : "=r"(r0), "=r"(r1), "=r"(r2), "=r"(r3) : "r"(addr))
#define LDSM_X4T(r0, r1, r2, r3, addr) \
    asm volatile("ldmatrix.sync.aligned.m8n8.x4.trans.shared.b16 {%0,%1,%2,%3}, [%4];" \
                 : "=r"(r0), "=r"(r1), "=r"(r2), "=r"(r3) : "r"(addr))
#define MMA16816(c, a, b0, b1) \
    asm volatile("mma.sync.aligned.m16n8k16.row.col.f32.bf16.bf16.f32 " \
                 "{%0,%1,%2,%3}, {%4,%5,%6,%7}, {%8,%9}, {%0,%1,%2,%3};" \
                 : "+f"((c)[0]), "+f"((c)[1]), "+f"((c)[2]), "+f"((c)[3]) \
                 : "r"((a)[0]), "r"((a)[1]), "r"((a)[2]), "r"((a)[3]), \
                   "r"(b0), "r"(b1))

// ---------------- prep: split-convert inputs and weights ----------------
__global__ void k_prep_x(const float4* __restrict__ sc, const float4* __restrict__ fc) {
    int b = blockIdx.y;
    const float4* src = b ? fc : sc;
    size_t i = (size_t)blockIdx.x * 256 + threadIdx.x;  // over N*HID/4
    if (i >= (size_t)N_NODESC * HID / 4) return;
    float4 v = src[i];
    uint4 o = make_uint4(packsplit(v.x), packsplit(v.y), packsplit(v.z), packsplit(v.w));
    ((uint4*)g_xs[b])[i] = o;
}
__global__ void k_prep_w(const float* __restrict__ scW, const float* __restrict__ fcW) {
    int b = blockIdx.y;
    const float* W = b ? fcW : scW;
    int i = blockIdx.x * 256 + threadIdx.x;
    if (i < NLAYER * HID * HID) g_ws[b][i] = packsplit(W[i]);
}

// ---------------- CSR build (both branches, grid.y = branch) ----------------
__global__ void k_zero_counts() {
    int i = blockIdx.x * blockDim.x + threadIdx.x;
    if (i <= N_NODESC) g_off[blockIdx.y][i] = 0;
}
__global__ void k_hist(const int* __restrict__ sc_ei, const int* __restrict__ fc_ei) {
    int b = blockIdx.y;
    const int* dst = (b ? fc_ei : sc_ei) + N_EDGESC;
    for (int e = blockIdx.x * blockDim.x + threadIdx.x; e < N_EDGESC;
         e += gridDim.x * blockDim.x)
        atomicAdd(&g_off[b][dst[e]], 1);
}
__global__ void k_scan1() {
    __shared__ int ws[32];
    int b = blockIdx.y;
    int t = threadIdx.x;
    int lane = t & 31, w = t >> 5;
    int idx = blockIdx.x * 1024 + t;
    int v = (idx < N_NODESC) ? g_off[b][idx] : 0;
    if (idx < N_NODESC) g_dis[b][idx] = rsqrtf((float)v + 1.0f);
    int x = v;
#pragma unroll
    for (int off = 1; off < 32; off <<= 1) {
        int n = __shfl_up_sync(0xffffffffu, x, off);
        if (lane >= off) x += n;
    }
    if (lane == 31) ws[w] = x;
    __syncthreads();
    if (w == 0) {
        int y = ws[lane];
#pragma unroll
        for (int off = 1; off < 32; off <<= 1) {
            int n = __shfl_up_sync(0xffffffffu, y, off);
            if (lane >= off) y += n;
        }
        ws[lane] = y;
    }
    __syncthreads();
    int inc = x + ((w > 0) ? ws[w - 1] : 0);
    if (idx < N_NODESC) g_off[b][idx] = inc - v;
    if (t == 1023) g_bsum[b][blockIdx.x] = inc;
}
__global__ void k_scan2() {   // grid (1,2), 32 threads: warp scan of block sums
    int b = blockIdx.y, lane = threadIdx.x;
    int carry = 0;
    for (int c = 0; c < SCAN_BLOCKS; c += 32) {
        int i = c + lane;
        int v = (i < SCAN_BLOCKS) ? g_bsum[b][i] : 0;
        int x = v;
#pragma unroll
        for (int off = 1; off < 32; off <<= 1) {
            int n = __shfl_up_sync(0xffffffffu, x, off);
            if (lane >= off) x += n;
        }
        if (i < SCAN_BLOCKS) g_bsum[b][i] = x - v + carry;
        carry += __shfl_sync(0xffffffffu, x, 31);
    }
    if (lane == 0) g_off[b][N_NODESC] = N_EDGESC;
}
__global__ void k_scan3() {
    int b = blockIdx.y;
    int idx = blockIdx.x * 1024 + threadIdx.x;
    if (idx < N_NODESC) {
        int o = g_off[b][idx] + g_bsum[b][idx >> 10];
        g_off[b][idx] = o;
        g_cur[b][idx] = o;
    }
}
__global__ void k_bucket(const int* __restrict__ sc_ei, const int* __restrict__ fc_ei) {
    int b = blockIdx.y;
    const int* src = (b ? fc_ei : sc_ei);
    const int* dst = src + N_EDGESC;
    for (int e = blockIdx.x * blockDim.x + threadIdx.x; e < N_EDGESC;
         e += gridDim.x * blockDim.x) {
        int d = dst[e];
        int s = src[e];
        int slot = atomicAdd(&g_cur[b][d], 1);
        float w = g_dis[b][s] * g_dis[b][d];
        g_ew[b][slot] = make_int2(s, __float_as_int(w));
    }
}

// ---------------- tensor-core GEMM: H = X @ W, bf16 3-term split ----------------
#define APITCH 136
#define TILE_B (128 * APITCH * 2)      // 34816 bytes
#define OFF_AHI 0
#define OFF_ALO TILE_B
#define OFF_BHI (2 * TILE_B)
#define OFF_BLO (3 * TILE_B)
#define GEMM_SMEM (4 * TILE_B)         // 139264

__global__ void __launch_bounds__(256, 1)
k_gemm_mma(int layer, int nrows) {
    extern __shared__ char sm[];
    uint32_t base = smem_u32(sm);
    int b = blockIdx.y;
    int tid = threadIdx.x;
    int r0 = blockIdx.x * 128;
    const uint32_t* Xp = g_xs[b];
    const uint32_t* Wp = g_ws[b] + layer * HID * HID;

    // ---- unpack W tile -> Bhi/Blo (B[k][n]) ----
    for (int g = tid; g < 128 * 32; g += 256) {
        int k = g >> 5, q = g & 31;
        uint4 p = ((const uint4*)Wp)[k * 32 + q];
        uint32_t off = (uint32_t)(k * APITCH + q * 4) * 2u;
        *(uint2*)(sm + OFF_BHI + off) =
            make_uint2(__byte_perm(p.x, p.y, 0x5410), __byte_perm(p.z, p.w, 0x5410));
        *(uint2*)(sm + OFF_BLO + off) =
            make_uint2(__byte_perm(p.x, p.y, 0x7632), __byte_perm(p.z, p.w, 0x7632));
    }
    // ---- unpack X tile -> Ahi/Alo ----
    for (int g = tid; g < 128 * 32; g += 256) {
        int row = g >> 5, q = g & 31;
        int grow = r0 + row;
        uint4 p = (grow < nrows)
            ? ((const uint4*)(Xp + (size_t)grow * HID))[q]
            : make_uint4(0u, 0u, 0u, 0u);
        uint32_t off = (uint32_t)(row * APITCH + q * 4) * 2u;
        *(uint2*)(sm + OFF_AHI + off) =
            make_uint2(__byte_perm(p.x, p.y, 0x5410), __byte_perm(p.z, p.w, 0x5410));
        *(uint2*)(sm + OFF_ALO + off) =
            make_uint2(__byte_perm(p.x, p.y, 0x7632), __byte_perm(p.z, p.w, 0x7632));
    }
    __syncthreads();

    int w = tid >> 5, lane = tid & 31;
    int wm = w & 3, wn = w >> 2;
    int rbase = wm * 32, cbase = wn * 64;

    float acc[2][8][4];
#pragma unroll
    for (int m = 0; m < 2; m++)
#pragma unroll
        for (int n = 0; n < 8; n++)
#pragma unroll
            for (int c = 0; c < 4; c++) acc[m][n][c] = 0.f;

    int a_r = lane & 15, a_c = (lane >> 4) * 8;
    int b_kr = ((lane >> 3) & 1) * 8 + (lane & 7), b_c = (lane >> 4) * 8;

#pragma unroll
    for (int ks = 0; ks < 8; ++ks) {
        int k0 = ks * 16;
        uint32_t ahi[2][4], alo[2][4];
#pragma unroll
        for (int m = 0; m < 2; ++m) {
            uint32_t aoff = (uint32_t)((rbase + m * 16 + a_r) * APITCH + k0 + a_c) * 2u;
            LDSM_X4(ahi[m][0], ahi[m][1], ahi[m][2], ahi[m][3], base + OFF_AHI + aoff);
            LDSM_X4(alo[m][0], alo[m][1], alo[m][2], alo[m][3], base + OFF_ALO + aoff);
        }
#pragma unroll
        for (int n2 = 0; n2 < 4; ++n2) {
            int n0 = cbase + n2 * 16;
            uint32_t boff = (uint32_t)((k0 + b_kr) * APITCH + n0 + b_c) * 2u;
            uint32_t bh0, bh1, bh2, bh3, bl0, bl1, bl2, bl3;
            LDSM_X4T(bh0, bh1, bh2, bh3, base + OFF_BHI + boff);
            LDSM_X4T(bl0, bl1, bl2, bl3, base + OFF_BLO + boff);
#pragma unroll
            for (int m = 0; m < 2; ++m) {
                MMA16816(acc[m][n2 * 2], ahi[m], bh0, bh1);
                MMA16816(acc[m][n2 * 2 + 1], ahi[m], bh2, bh3);
                MMA16816(acc[m][n2 * 2], ahi[m], bl0, bl1);
                MMA16816(acc[m][n2 * 2 + 1], ahi[m], bl2, bl3);
                MMA16816(acc[m][n2 * 2], alo[m], bh0, bh1);
                MMA16816(acc[m][n2 * 2 + 1], alo[m], bh2, bh3);
            }
        }
    }

    // ---- epilogue: write h as fp16 pairs ----
    __half* Hp = g_h[b];
#pragma unroll
    for (int m = 0; m < 2; ++m) {
        int rA = r0 + rbase + m * 16 + (lane >> 2);
        int rB = rA + 8;
#pragma unroll
        for (int ng = 0; ng < 8; ++ng) {
            int col = cbase + ng * 8 + (lane & 3) * 2;
            if (rA < nrows) {
                __half2 hv = __floats2half2_rn(acc[m][ng][0], acc[m][ng][1]);
                *(__half2*)(Hp + (size_t)rA * HID + col) = hv;
            }
            if (rB < nrows) {
                __half2 hv = __floats2half2_rn(acc[m][ng][2], acc[m][ng][3]);
                *(__half2*)(Hp + (size_t)rB * HID + col) = hv;
            }
        }
    }
}

// ---------------- fused aggregation: xs = packsplit(relu(segsum + self + bias)) ----
__global__ void __launch_bounds__(256)
k_agg(const float* __restrict__ sc_b, const float* __restrict__ fc_b, int layer) {
    int b = blockIdx.y;
    int node = (blockIdx.x * blockDim.x + threadIdx.x) >> 5;
    int lane = threadIdx.x & 31;
    if (node >= N_NODESC) return;
    const __half* Hp = g_h[b];
    const float* bias = (b ? fc_b : sc_b) + layer * HID;
    float dd = g_dis[b][node];
    int beg = g_off[b][node], end = g_off[b][node + 1];
    float ax = 0.f, ay = 0.f, az = 0.f, aw = 0.f;
    int e = beg;
    for (; e + 1 < end; e += 2) {
        int2 p0 = g_ew[b][e];
        int2 p1 = g_ew[b][e + 1];
        float w0 = __int_as_float(p0.y);
        float w1 = __int_as_float(p1.y);
        uint2 r0v = *(const uint2*)(Hp + (size_t)p0.x * HID + lane * 4);
        uint2 r1v = *(const uint2*)(Hp + (size_t)p1.x * HID + lane * 4);
        float2 f0 = __half22float2(*(__half2*)&r0v.x);
        float2 f1 = __half22float2(*(__half2*)&r0v.y);
        float2 f2 = __half22float2(*(__half2*)&r1v.x);
        float2 f3 = __half22float2(*(__half2*)&r1v.y);
        ax = fmaf(f0.x, w0, ax); ay = fmaf(f0.y, w0, ay);
        az = fmaf(f1.x, w0, az); aw = fmaf(f1.y, w0, aw);
        ax = fmaf(f2.x, w1, ax); ay = fmaf(f2.y, w1, ay);
        az = fmaf(f3.x, w1, az); aw = fmaf(f3.y, w1, aw);
    }
    if (e < end) {
        int2 p0 = g_ew[b][e];
        float w0 = __int_as_float(p0.y);
        uint2 r0v = *(const uint2*)(Hp + (size_t)p0.x * HID + lane * 4);
        float2 f0 = __half22float2(*(__half2*)&r0v.x);
        float2 f1 = __half22float2(*(__half2*)&r0v.y);
        ax = fmaf(f0.x, w0, ax); ay = fmaf(f0.y, w0, ay);
        az = fmaf(f1.x, w0, az); aw = fmaf(f1.y, w0, aw);
    }
    uint2 rs = *(const uint2*)(Hp + (size_t)node * HID + lane * 4);
    float2 s0 = __half22float2(*(__half2*)&rs.x);
    float2 s1 = __half22float2(*(__half2*)&rs.y);
    float sn = dd * dd;
    float4 bb = *(const float4*)(bias + lane * 4);
    ax = fmaxf(fmaf(s0.x, sn, ax) + bb.x, 0.f);
    ay = fmaxf(fmaf(s0.y, sn, ay) + bb.y, 0.f);
    az = fmaxf(fmaf(s1.x, sn, az) + bb.z, 0.f);
    aw = fmaxf(fmaf(s1.y, sn, aw) + bb.w, 0.f);
    uint4 st = make_uint4(packsplit(ax), packsplit(ay), packsplit(az), packsplit(aw));
    *(uint4*)(g_xs[b] + (size_t)node * HID + lane * 4) = st;
}

// ---------------- pooling: block per (graph, branch) ----------------
__global__ void __launch_bounds__(128)
k_pool2(const int* __restrict__ batch) {
    int g = blockIdx.x, b = blockIdx.y, t = threadIdx.x;
    __shared__ int s_lo, s_hi;
    if (t == 0) {
        int lo = 0, hi = N_NODESC;
        while (lo < hi) { int m = (lo + hi) >> 1; if (batch[m] < g) lo = m + 1; else hi = m; }
        s_lo = lo;
    }
    if (t == 32) {
        int lo = 0, hi = N_NODESC;
        while (lo < hi) { int m = (lo + hi) >> 1; if (batch[m] < g + 1) lo = m + 1; else hi = m; }
        s_hi = lo;
    }
    __syncthreads();
    int lo = s_lo, hi = s_hi;
    const uint32_t* Xp = g_xs[b];
    float acc = 0.f;
    int n = lo;
    for (; n + 3 < hi; n += 4) {
        float v0 = unpacksplit(Xp[(size_t)n * HID + t]);
        float v1 = unpacksplit(Xp[(size_t)(n + 1) * HID + t]);
        float v2 = unpacksplit(Xp[(size_t)(n + 2) * HID + t]);
        float v3 = unpacksplit(Xp[(size_t)(n + 3) * HID + t]);
        acc += (v0 + v1) + (v2 + v3);
    }
    for (; n < hi; ++n) acc += unpacksplit(Xp[(size_t)n * HID + t]);
    (b ? g_fcg : g_scg)[g * HID + t] = acc;
}

// ---------------- head ----------------
__global__ void k_head(const float* __restrict__ fc1W, const float* __restrict__ fc1b) {
    int b = blockIdx.x, t = threadIdx.x;
    __shared__ float s[256];
    __shared__ float red[128];
    __shared__ float inv_ns, inv_nf;
    s[t] = g_scg[b * HID + t];
    s[128 + t] = g_fcg[b * HID + t];
    __syncthreads();
    red[t] = s[t] * s[t];
    __syncthreads();
    for (int off = 64; off > 0; off >>= 1) {
        if (t < off) red[t] += red[t + off];
        __syncthreads();
    }
    if (t == 0) inv_ns = 1.0f / fmaxf(sqrtf(red[0]), 1e-12f);
    __syncthreads();
    red[t] = s[128 + t] * s[128 + t];
    __syncthreads();
    for (int off = 64; off > 0; off >>= 1) {
        if (t < off) red[t] += red[t + off];
        __syncthreads();
    }
    if (t == 0) inv_nf = 1.0f / fmaxf(sqrtf(red[0]), 1e-12f);
    __syncthreads();
    float acc = 0.f;
#pragma unroll 8
    for (int k = 0; k < 256; k++) acc = fmaf(s[k], fc1W[k * HID + t], acc);
    acc += fc1b[t];
    g_z[b * HID + t] = fmaxf(acc, 0.f);
    g_scn[b * HID + t] = s[t] * inv_ns;
    g_fcn[b * HID + t] = s[128 + t] * inv_nf;
}

// ---------------- contrastive row losses ----------------
__global__ void k_loss() {
    int i = blockIdx.x, j = threadIdx.x;
    __shared__ float sni[HID], fni[HID];
    __shared__ float red[256];
    __shared__ float diag_sc, diag_fc, Msc, Mfc, Ssc, Sfc;
    if (j < HID) { sni[j] = g_scn[i * HID + j]; fni[j] = g_fcn[i * HID + j]; }
    __syncthreads();
    float dsf = 0.f, dss = 0.f, dfs = 0.f, dff = 0.f;
    const float* srow = &g_scn[j * HID];
    const float* frow = &g_fcn[j * HID];
#pragma unroll 4
    for (int k = 0; k < HID; k++) {
        float sj = srow[k], fj = frow[k], si = sni[k], fi = fni[k];
        dsf = fmaf(si, fj, dsf);
        dss = fmaf(si, sj, dss);
        dfs = fmaf(fi, sj, dfs);
        dff = fmaf(fi, fj, dff);
    }
    const float tt = 2.0f;
    float e1 = dsf * tt;
    float e2 = (j == i) ? 0.f : 0.8f * tt * dss;
    float f1 = dfs * tt;
    float f2 = (j == i) ? 0.f : 0.8f * tt * dff;
    if (j == i) { diag_sc = e1; diag_fc = f1; }
    red[j] = fmaxf(e1, e2);
    __syncthreads();
    for (int off = 128; off > 0; off >>= 1) {
        if (j < off) red[j] = fmaxf(red[j], red[j + off]);
        __syncthreads();
    }
    if (j == 0) Msc = red[0];
    __syncthreads();
    red[j] = expf(e1 - Msc) + expf(e2 - Msc);
    __syncthreads();
    for (int off = 128; off > 0; off >>= 1) {
        if (j < off) red[j] += red[j + off];
        __syncthreads();
    }
    if (j == 0) Ssc = red[0];
    __syncthreads();
    red[j] = fmaxf(f1, f2);
    __syncthreads();
    for (int off = 128; off > 0; off >>= 1) {
        if (j < off) red[j] = fmaxf(red[j], red[j + off]);
        __syncthreads();
    }
    if (j == 0) Mfc = red[0];
    __syncthreads();
    red[j] = expf(f1 - Mfc) + expf(f2 - Mfc);
    __syncthreads();
    for (int off = 128; off > 0; off >>= 1) {
        if (j < off) red[j] += red[j + off];
        __syncthreads();
    }
    if (j == 0) {
        Sfc = red[0];
        g_loss[i] = (Msc + logf(Ssc)) - diag_sc;
        g_loss[NGRAPH + i] = (Mfc + logf(Sfc)) - diag_fc;
    }
}

// ---------------- final ----------------
__global__ void k_final(const float* __restrict__ fc2W, const float* __restrict__ fc2b,
                        float* __restrict__ out) {
    __shared__ float red[256];
    __shared__ float scalar;
    int t = threadIdx.x;
    red[t] = g_loss[t] + g_loss[NGRAPH + t];
    __syncthreads();
    for (int off = 128; off > 0; off >>= 1) {
        if (t < off) red[t] += red[t + off];
        __syncthreads();
    }
    if (t == 0) scalar = red[0] / (2.0f * NGRAPH);
    __syncthreads();
    float l0 = fc2b[0], l1 = fc2b[1];
    const float* z = &g_z[t * HID];
#pragma unroll 4
    for (int k = 0; k < HID; k++) {
        float zv = z[k];
        l0 = fmaf(zv, fc2W[2 * k], l0);
        l1 = fmaf(zv, fc2W[2 * k + 1], l1);
    }
    float m = fmaxf(l0, l1);
    float lse = m + logf(expf(l0 - m) + expf(l1 - m));
    out[2 * t] = l0 - lse + scalar;
    out[2 * t + 1] = l1 - lse + scalar;
}

// ---------------- host side ----------------
extern "C" void kernel_launch(void* const* d_in, const int* in_sizes, int n_in,
                              void* d_out, int out_size) {
    const float *sc_x = 0, *fc_x = 0, *sc_W = 0, *sc_b = 0, *fc_W = 0, *fc_b = 0;
    const float *fc1W = 0, *fc1b = 0, *fc2W = 0, *fc2b = 0;
    const int *sc_ei = 0, *fc_ei = 0, *batch = 0;
    for (int i = 0; i < n_in; i++) {
        long s = in_sizes[i];
        const void* p = d_in[i];
        if (s == (long)N_NODESC * HID) {
            if (!sc_x) sc_x = (const float*)p; else fc_x = (const float*)p;
        } else if (s == 2L * N_EDGESC) {
            if (!sc_ei) sc_ei = (const int*)p; else fc_ei = (const int*)p;
        } else if (s == N_NODESC) {
            batch = (const int*)p;
        } else if (s == (long)NLAYER * HID * HID) {
            if (!sc_W) sc_W = (const float*)p; else fc_W = (const float*)p;
        } else if (s == (long)NLAYER * HID) {
            if (!sc_b) sc_b = (const float*)p; else fc_b = (const float*)p;
        } else if (s == 2L * HID * HID) {
            fc1W = (const float*)p;
        } else if (s == HID) {
            fc1b = (const float*)p;
        } else if (s == 2L * HID) {
            fc2W = (const float*)p;
        } else if (s == 2) {
            fc2b = (const float*)p;
        }
    }
    cudaFuncSetAttribute(k_gemm_mma, cudaFuncAttributeMaxDynamicSharedMemorySize,
                         GEMM_SMEM);

    k_prep_x<<<dim3((N_NODESC * HID / 4 + 255) / 256, 2), 256>>>(
        (const float4*)sc_x, (const float4*)fc_x);
    k_prep_w<<<dim3((NLAYER * HID * HID + 255) / 256, 2), 256>>>(sc_W, fc_W);
    k_zero_counts<<<dim3((N_NODESC + 256) / 256, 2), 256>>>();
    k_hist<<<dim3(1024, 2), 256>>>(sc_ei, fc_ei);
    k_scan1<<<dim3(SCAN_BLOCKS, 2), 1024>>>();
    k_scan2<<<dim3(1, 2), 32>>>();
    k_scan3<<<dim3(SCAN_BLOCKS, 2), 1024>>>();
    k_bucket<<<dim3(1024, 2), 256>>>(sc_ei, fc_ei);
    for (int l = 0; l < NLAYER; ++l) {
        k_gemm_mma<<<dim3(NTILES, 2), 256, GEMM_SMEM>>>(l, N_NODESC);
        k_agg<<<dim3((N_NODESC * 32 + 255) / 256, 2), 256>>>(sc_b, fc_b, l);
    }
    k_pool2<<<dim3(NGRAPH, 2), 128>>>(batch);
    k_head<<<NGRAPH, 128>>>(fc1W, fc1b);
    k_loss<<<NGRAPH, 256>>>();
    k_final<<<1, 256>>>(fc2W, fc2b, (float*)d_out);
}

// round 7
// speedup vs baseline: 1.9706x; 1.2759x over previous
#include <cuda_runtime.h>
#include <cuda_bf16.h>
#include <cuda_fp16.h>
#include <math.h>
#include <stdint.h>

#define N_NODESC 100000
#define N_EDGESC 1600000
#define HID 128
#define NGRAPH 256
#define NLAYER 3
#define SCAN_BLOCKS ((N_NODESC + 1023) / 1024)   // 98
#define NT64 ((N_NODESC + 63) / 64)              // 1563

// ---------------- scratch (static device globals; no allocation) ----------------
__device__ __half    g_h[2][(size_t)N_NODESC * HID];   // GEMM output (fp16)
__device__ uint32_t  g_xs[2][(size_t)N_NODESC * HID];  // activations, packed bf16 hi|lo
__device__ uint32_t  g_ws[2][NLAYER * HID * HID];      // W, packed bf16 hi|lo
__device__ float     g_dis[2][N_NODESC];
__device__ int       g_off[2][N_NODESC + 1];
__device__ int       g_cur[2][N_NODESC];
__device__ int2      g_ew[2][N_EDGESC];                // {src, enorm}
__device__ int       g_bsum[2][SCAN_BLOCKS + 1];
__device__ float     g_scg[NGRAPH * HID];
__device__ float     g_fcg[NGRAPH * HID];
__device__ float     g_z[NGRAPH * HID];
__device__ float     g_scn[NGRAPH * HID];
__device__ float     g_fcn[NGRAPH * HID];
__device__ float     g_loss[2 * NGRAPH];

// ---------------- helpers ----------------
__device__ __forceinline__ uint32_t smem_u32(const void* p) {
    uint32_t a;
    asm("{ .reg .u64 t; cvta.to.shared.u64 t, %1; cvt.u32.u64 %0, t; }"
        : "=r"(a) : "l"(p));
    return a;
}
__device__ __forceinline__ uint32_t packsplit(float v) {
    __nv_bfloat16 h = __float2bfloat16_rn(v);
    float lo = v - __bfloat162float(h);
    __nv_bfloat16 l = __float2bfloat16_rn(lo);
    return (uint32_t)__bfloat16_as_ushort(h) |
           ((uint32_t)__bfloat16_as_ushort(l) << 16);
}
__device__ __forceinline__ float unpacksplit(uint32_t p) {
    return __bfloat162float(__ushort_as_bfloat16((unsigned short)(p & 0xffffu))) +
           __bfloat162float(__ushort_as_bfloat16((unsigned short)(p >> 16)));
}
#define LDSM_X4(r0, r1, r2, r3, addr) \
    asm volatile("ldmatrix.sync.aligned.m8n8.x4.shared.b16 {%0,%1,%2,%3}, [%4];" \
                 : "=r"(r0), "=r"(r1), "=r"(r2), "=r"(r3) : "r"(addr))
#define LDSM_X4T(r0, r1, r2, r3, addr) \
    asm volatile("ldmatrix.sync.aligned.m8n8.x4.trans.shared.b16 {%0,%1,%2,%3}, [%4];" \
                 : "=r"(r0), "=r"(r1), "=r"(r2), "=r"(r3) : "r"(addr))
#define MMA16816(c, a, b0, b1) \
    asm volatile("mma.sync.aligned.m16n8k16.row.col.f32.bf16.bf16.f32 " \
                 "{%0,%1,%2,%3}, {%4,%5,%6,%7}, {%8,%9}, {%0,%1,%2,%3};" \
                 : "+f"((c)[0]), "+f"((c)[1]), "+f"((c)[2]), "+f"((c)[3]) \
                 : "r"((a)[0]), "r"((a)[1]), "r"((a)[2]), "r"((a)[3]), \
                   "r"(b0), "r"(b1))

// ---------------- prep: split-convert inputs and weights ----------------
__global__ void k_prep_x(const float4* __restrict__ sc, const float4* __restrict__ fc) {
    int b = blockIdx.y;
    const float4* src = b ? fc : sc;
    size_t i = (size_t)blockIdx.x * 256 + threadIdx.x;
    if (i >= (size_t)N_NODESC * HID / 4) return;
    float4 v = src[i];
    uint4 o = make_uint4(packsplit(v.x), packsplit(v.y), packsplit(v.z), packsplit(v.w));
    ((uint4*)g_xs[b])[i] = o;
}
__global__ void k_prep_w(const float* __restrict__ scW, const float* __restrict__ fcW) {
    int b = blockIdx.y;
    const float* W = b ? fcW : scW;
    int i = blockIdx.x * 256 + threadIdx.x;
    if (i < NLAYER * HID * HID) g_ws[b][i] = packsplit(W[i]);
}

// ---------------- CSR build ----------------
__global__ void k_zero_counts() {
    int i = blockIdx.x * blockDim.x + threadIdx.x;
    if (i <= N_NODESC) g_off[blockIdx.y][i] = 0;
}
__global__ void k_hist(const int* __restrict__ sc_ei, const int* __restrict__ fc_ei) {
    int b = blockIdx.y;
    const int* dst = (b ? fc_ei : sc_ei) + N_EDGESC;
    for (int e = blockIdx.x * blockDim.x + threadIdx.x; e < N_EDGESC;
         e += gridDim.x * blockDim.x)
        atomicAdd(&g_off[b][dst[e]], 1);
}
__global__ void k_scan1() {
    __shared__ int ws[32];
    int b = blockIdx.y;
    int t = threadIdx.x;
    int lane = t & 31, w = t >> 5;
    int idx = blockIdx.x * 1024 + t;
    int v = (idx < N_NODESC) ? g_off[b][idx] : 0;
    if (idx < N_NODESC) g_dis[b][idx] = rsqrtf((float)v + 1.0f);
    int x = v;
#pragma unroll
    for (int off = 1; off < 32; off <<= 1) {
        int n = __shfl_up_sync(0xffffffffu, x, off);
        if (lane >= off) x += n;
    }
    if (lane == 31) ws[w] = x;
    __syncthreads();
    if (w == 0) {
        int y = ws[lane];
#pragma unroll
        for (int off = 1; off < 32; off <<= 1) {
            int n = __shfl_up_sync(0xffffffffu, y, off);
            if (lane >= off) y += n;
        }
        ws[lane] = y;
    }
    __syncthreads();
    int inc = x + ((w > 0) ? ws[w - 1] : 0);
    if (idx < N_NODESC) g_off[b][idx] = inc - v;
    if (t == 1023) g_bsum[b][blockIdx.x] = inc;
}
__global__ void k_scan2() {
    int b = blockIdx.y, lane = threadIdx.x;
    int carry = 0;
    for (int c = 0; c < SCAN_BLOCKS; c += 32) {
        int i = c + lane;
        int v = (i < SCAN_BLOCKS) ? g_bsum[b][i] : 0;
        int x = v;
#pragma unroll
        for (int off = 1; off < 32; off <<= 1) {
            int n = __shfl_up_sync(0xffffffffu, x, off);
            if (lane >= off) x += n;
        }
        if (i < SCAN_BLOCKS) g_bsum[b][i] = x - v + carry;
        carry += __shfl_sync(0xffffffffu, x, 31);
    }
    if (lane == 0) g_off[b][N_NODESC] = N_EDGESC;
}
__global__ void k_scan3() {
    int b = blockIdx.y;
    int idx = blockIdx.x * 1024 + threadIdx.x;
    if (idx < N_NODESC) {
        int o = g_off[b][idx] + g_bsum[b][idx >> 10];
        g_off[b][idx] = o;
        g_cur[b][idx] = o;
    }
}
__global__ void k_bucket(const int* __restrict__ sc_ei, const int* __restrict__ fc_ei) {
    int b = blockIdx.y;
    const int* src = (b ? fc_ei : sc_ei);
    const int* dst = src + N_EDGESC;
    for (int e = blockIdx.x * blockDim.x + threadIdx.x; e < N_EDGESC;
         e += gridDim.x * blockDim.x) {
        int d = dst[e];
        int s = src[e];
        int slot = atomicAdd(&g_cur[b][d], 1);
        float w = g_dis[b][s] * g_dis[b][d];
        g_ew[b][slot] = make_int2(s, __float_as_int(w));
    }
}

// ---------------- persistent tensor-core GEMM: H = X @ W, bf16 3-term split ----
// SMEM: Bhi/Blo [128 k][136] bf16; Ahi/Alo [64 rows][136] bf16. Total 102 KB.
#define APITCH 136
#define BTILE_B (128 * APITCH * 2)     // 34816
#define ATILE_B (64 * APITCH * 2)      // 17408
#define OFF_BHI 0
#define OFF_BLO BTILE_B
#define OFF_AHI (2 * BTILE_B)
#define OFF_ALO (2 * BTILE_B + ATILE_B)
#define GEMM_SMEM (2 * BTILE_B + 2 * ATILE_B)   // 104448

__global__ void __launch_bounds__(256, 2)
k_gemm_mma(int layer, int nrows) {
    extern __shared__ char sm[];
    uint32_t base = smem_u32(sm);
    int b = blockIdx.y;
    int tid = threadIdx.x;
    const uint32_t* Xp = g_xs[b];
    const uint32_t* Wp = g_ws[b] + layer * HID * HID;
    __half* Hp = g_h[b];

    // ---- unpack W -> Bhi/Blo once per CTA ----
    for (int g = tid; g < 128 * 32; g += 256) {
        int k = g >> 5, q = g & 31;
        uint4 p = ((const uint4*)Wp)[k * 32 + q];
        uint32_t off = (uint32_t)(k * APITCH + q * 4) * 2u;
        *(uint2*)(sm + OFF_BHI + off) =
            make_uint2(__byte_perm(p.x, p.y, 0x5410), __byte_perm(p.z, p.w, 0x5410));
        *(uint2*)(sm + OFF_BLO + off) =
            make_uint2(__byte_perm(p.x, p.y, 0x7632), __byte_perm(p.z, p.w, 0x7632));
    }

    int w = tid >> 5, lane = tid & 31;
    int wm = w & 1, wn = w >> 1;            // 2 row-groups x 4 col-groups
    int rbase = wm * 32, cbase = wn * 32;
    int a_r = lane & 15, a_c = (lane >> 4) * 8;
    int b_kr = ((lane >> 3) & 1) * 8 + (lane & 7), b_c = (lane >> 4) * 8;

    for (int tile = blockIdx.x; tile < NT64; tile += gridDim.x) {
        int r0 = tile * 64;
        __syncthreads();   // previous iteration's mainloop done before A overwrite
        // ---- unpack X tile (64 rows) -> Ahi/Alo ----
        for (int g = tid; g < 64 * 32; g += 256) {
            int row = g >> 5, q = g & 31;
            int grow = r0 + row;
            uint4 p = (grow < nrows)
                ? ((const uint4*)(Xp + (size_t)grow * HID))[q]
                : make_uint4(0u, 0u, 0u, 0u);
            uint32_t off = (uint32_t)(row * APITCH + q * 4) * 2u;
            *(uint2*)(sm + OFF_AHI + off) =
                make_uint2(__byte_perm(p.x, p.y, 0x5410), __byte_perm(p.z, p.w, 0x5410));
            *(uint2*)(sm + OFF_ALO + off) =
                make_uint2(__byte_perm(p.x, p.y, 0x7632), __byte_perm(p.z, p.w, 0x7632));
        }
        __syncthreads();

        float acc[2][4][4];
#pragma unroll
        for (int m = 0; m < 2; m++)
#pragma unroll
            for (int n = 0; n < 4; n++)
#pragma unroll
                for (int c = 0; c < 4; c++) acc[m][n][c] = 0.f;

#pragma unroll
        for (int ks = 0; ks < 8; ++ks) {
            int k0 = ks * 16;
            uint32_t ahi[2][4], alo[2][4];
#pragma unroll
            for (int m = 0; m < 2; ++m) {
                uint32_t aoff =
                    (uint32_t)((rbase + m * 16 + a_r) * APITCH + k0 + a_c) * 2u;
                LDSM_X4(ahi[m][0], ahi[m][1], ahi[m][2], ahi[m][3], base + OFF_AHI + aoff);
                LDSM_X4(alo[m][0], alo[m][1], alo[m][2], alo[m][3], base + OFF_ALO + aoff);
            }
#pragma unroll
            for (int n2 = 0; n2 < 2; ++n2) {
                int n0 = cbase + n2 * 16;
                uint32_t boff = (uint32_t)((k0 + b_kr) * APITCH + n0 + b_c) * 2u;
                uint32_t bh0, bh1, bh2, bh3, bl0, bl1, bl2, bl3;
                LDSM_X4T(bh0, bh1, bh2, bh3, base + OFF_BHI + boff);
                LDSM_X4T(bl0, bl1, bl2, bl3, base + OFF_BLO + boff);
#pragma unroll
                for (int m = 0; m < 2; ++m) {
                    MMA16816(acc[m][n2 * 2], ahi[m], bh0, bh1);
                    MMA16816(acc[m][n2 * 2 + 1], ahi[m], bh2, bh3);
                    MMA16816(acc[m][n2 * 2], ahi[m], bl0, bl1);
                    MMA16816(acc[m][n2 * 2 + 1], ahi[m], bl2, bl3);
                    MMA16816(acc[m][n2 * 2], alo[m], bh0, bh1);
                    MMA16816(acc[m][n2 * 2 + 1], alo[m], bh2, bh3);
                }
            }
        }

        // ---- epilogue: write h as fp16 ----
#pragma unroll
        for (int m = 0; m < 2; ++m) {
            int rA = r0 + rbase + m * 16 + (lane >> 2);
            int rB = rA + 8;
#pragma unroll
            for (int ng = 0; ng < 4; ++ng) {
                int col = cbase + ng * 8 + (lane & 3) * 2;
                if (rA < nrows)
                    *(__half2*)(Hp + (size_t)rA * HID + col) =
                        __floats2half2_rn(acc[m][ng][0], acc[m][ng][1]);
                if (rB < nrows)
                    *(__half2*)(Hp + (size_t)rB * HID + col) =
                        __floats2half2_rn(acc[m][ng][2], acc[m][ng][3]);
            }
        }
    }
}

// ---------------- fused aggregation ----------------
__global__ void __launch_bounds__(256)
k_agg(const float* __restrict__ sc_b, const float* __restrict__ fc_b, int layer) {
    int b = blockIdx.y;
    int node = (blockIdx.x * blockDim.x + threadIdx.x) >> 5;
    int lane = threadIdx.x & 31;
    if (node >= N_NODESC) return;
    const __half* Hp = g_h[b];
    const int2* ew = g_ew[b];
    const float* bias = (b ? fc_b : sc_b) + layer * HID;
    float dd = g_dis[b][node];
    int beg = g_off[b][node], end = g_off[b][node + 1];
    float ax = 0.f, ay = 0.f, az = 0.f, aw = 0.f;
    int e = beg;
    for (; e + 3 < end; e += 4) {
        int2 p0 = ew[e], p1 = ew[e + 1], p2 = ew[e + 2], p3 = ew[e + 3];
        uint2 r0v = *(const uint2*)(Hp + (size_t)p0.x * HID + lane * 4);
        uint2 r1v = *(const uint2*)(Hp + (size_t)p1.x * HID + lane * 4);
        uint2 r2v = *(const uint2*)(Hp + (size_t)p2.x * HID + lane * 4);
        uint2 r3v = *(const uint2*)(Hp + (size_t)p3.x * HID + lane * 4);
        float w0 = __int_as_float(p0.y), w1 = __int_as_float(p1.y);
        float w2 = __int_as_float(p2.y), w3 = __int_as_float(p3.y);
        float2 f0 = __half22float2(*(__half2*)&r0v.x);
        float2 f1 = __half22float2(*(__half2*)&r0v.y);
        ax = fmaf(f0.x, w0, ax); ay = fmaf(f0.y, w0, ay);
        az = fmaf(f1.x, w0, az); aw = fmaf(f1.y, w0, aw);
        f0 = __half22float2(*(__half2*)&r1v.x);
        f1 = __half22float2(*(__half2*)&r1v.y);
        ax = fmaf(f0.x, w1, ax); ay = fmaf(f0.y, w1, ay);
        az = fmaf(f1.x, w1, az); aw = fmaf(f1.y, w1, aw);
        f0 = __half22float2(*(__half2*)&r2v.x);
        f1 = __half22float2(*(__half2*)&r2v.y);
        ax = fmaf(f0.x, w2, ax); ay = fmaf(f0.y, w2, ay);
        az = fmaf(f1.x, w2, az); aw = fmaf(f1.y, w2, aw);
        f0 = __half22float2(*(__half2*)&r3v.x);
        f1 = __half22float2(*(__half2*)&r3v.y);
        ax = fmaf(f0.x, w3, ax); ay = fmaf(f0.y, w3, ay);
        az = fmaf(f1.x, w3, az); aw = fmaf(f1.y, w3, aw);
    }
    for (; e < end; ++e) {
        int2 p0 = ew[e];
        float w0 = __int_as_float(p0.y);
        uint2 r0v = *(const uint2*)(Hp + (size_t)p0.x * HID + lane * 4);
        float2 f0 = __half22float2(*(__half2*)&r0v.x);
        float2 f1 = __half22float2(*(__half2*)&r0v.y);
        ax = fmaf(f0.x, w0, ax); ay = fmaf(f0.y, w0, ay);
        az = fmaf(f1.x, w0, az); aw = fmaf(f1.y, w0, aw);
    }
    uint2 rs = *(const uint2*)(Hp + (size_t)node * HID + lane * 4);
    float2 s0 = __half22float2(*(__half2*)&rs.x);
    float2 s1 = __half22float2(*(__half2*)&rs.y);
    float sn = dd * dd;
    float4 bb = *(const float4*)(bias + lane * 4);
    ax = fmaxf(fmaf(s0.x, sn, ax) + bb.x, 0.f);
    ay = fmaxf(fmaf(s0.y, sn, ay) + bb.y, 0.f);
    az = fmaxf(fmaf(s1.x, sn, az) + bb.z, 0.f);
    aw = fmaxf(fmaf(s1.y, sn, aw) + bb.w, 0.f);
    uint4 st = make_uint4(packsplit(ax), packsplit(ay), packsplit(az), packsplit(aw));
    *(uint4*)(g_xs[b] + (size_t)node * HID + lane * 4) = st;
}

// ---------------- pooling ----------------
__global__ void __launch_bounds__(128)
k_pool2(const int* __restrict__ batch) {
    int g = blockIdx.x, b = blockIdx.y, t = threadIdx.x;
    __shared__ int s_lo, s_hi;
    if (t == 0) {
        int lo = 0, hi = N_NODESC;
        while (lo < hi) { int m = (lo + hi) >> 1; if (batch[m] < g) lo = m + 1; else hi = m; }
        s_lo = lo;
    }
    if (t == 32) {
        int lo = 0, hi = N_NODESC;
        while (lo < hi) { int m = (lo + hi) >> 1; if (batch[m] < g + 1) lo = m + 1; else hi = m; }
        s_hi = lo;
    }
    __syncthreads();
    int lo = s_lo, hi = s_hi;
    const uint32_t* Xp = g_xs[b];
    float acc = 0.f;
    int n = lo;
    for (; n + 3 < hi; n += 4) {
        float v0 = unpacksplit(Xp[(size_t)n * HID + t]);
        float v1 = unpacksplit(Xp[(size_t)(n + 1) * HID + t]);
        float v2 = unpacksplit(Xp[(size_t)(n + 2) * HID + t]);
        float v3 = unpacksplit(Xp[(size_t)(n + 3) * HID + t]);
        acc += (v0 + v1) + (v2 + v3);
    }
    for (; n < hi; ++n) acc += unpacksplit(Xp[(size_t)n * HID + t]);
    (b ? g_fcg : g_scg)[g * HID + t] = acc;
}

// ---------------- head ----------------
__global__ void k_head(const float* __restrict__ fc1W, const float* __restrict__ fc1b) {
    int b = blockIdx.x, t = threadIdx.x;
    __shared__ float s[256];
    __shared__ float red[128];
    __shared__ float inv_ns, inv_nf;
    s[t] = g_scg[b * HID + t];
    s[128 + t] = g_fcg[b * HID + t];
    __syncthreads();
    red[t] = s[t] * s[t];
    __syncthreads();
    for (int off = 64; off > 0; off >>= 1) {
        if (t < off) red[t] += red[t + off];
        __syncthreads();
    }
    if (t == 0) inv_ns = 1.0f / fmaxf(sqrtf(red[0]), 1e-12f);
    __syncthreads();
    red[t] = s[128 + t] * s[128 + t];
    __syncthreads();
    for (int off = 64; off > 0; off >>= 1) {
        if (t < off) red[t] += red[t + off];
        __syncthreads();
    }
    if (t == 0) inv_nf = 1.0f / fmaxf(sqrtf(red[0]), 1e-12f);
    __syncthreads();
    float acc = 0.f;
#pragma unroll 8
    for (int k = 0; k < 256; k++) acc = fmaf(s[k], fc1W[k * HID + t], acc);
    acc += fc1b[t];
    g_z[b * HID + t] = fmaxf(acc, 0.f);
    g_scn[b * HID + t] = s[t] * inv_ns;
    g_fcn[b * HID + t] = s[128 + t] * inv_nf;
}

// ---------------- contrastive row losses ----------------
__global__ void k_loss() {
    int i = blockIdx.x, j = threadIdx.x;
    __shared__ float sni[HID], fni[HID];
    __shared__ float red[256];
    __shared__ float diag_sc, diag_fc, Msc, Mfc, Ssc, Sfc;
    if (j < HID) { sni[j] = g_scn[i * HID + j]; fni[j] = g_fcn[i * HID + j]; }
    __syncthreads();
    float dsf = 0.f, dss = 0.f, dfs = 0.f, dff = 0.f;
    const float* srow = &g_scn[j * HID];
    const float* frow = &g_fcn[j * HID];
#pragma unroll 4
    for (int k = 0; k < HID; k++) {
        float sj = srow[k], fj = frow[k], si = sni[k], fi = fni[k];
        dsf = fmaf(si, fj, dsf);
        dss = fmaf(si, sj, dss);
        dfs = fmaf(fi, sj, dfs);
        dff = fmaf(fi, fj, dff);
    }
    const float tt = 2.0f;
    float e1 = dsf * tt;
    float e2 = (j == i) ? 0.f : 0.8f * tt * dss;
    float f1 = dfs * tt;
    float f2 = (j == i) ? 0.f : 0.8f * tt * dff;
    if (j == i) { diag_sc = e1; diag_fc = f1; }
    red[j] = fmaxf(e1, e2);
    __syncthreads();
    for (int off = 128; off > 0; off >>= 1) {
        if (j < off) red[j] = fmaxf(red[j], red[j + off]);
        __syncthreads();
    }
    if (j == 0) Msc = red[0];
    __syncthreads();
    red[j] = expf(e1 - Msc) + expf(e2 - Msc);
    __syncthreads();
    for (int off = 128; off > 0; off >>= 1) {
        if (j < off) red[j] += red[j + off];
        __syncthreads();
    }
    if (j == 0) Ssc = red[0];
    __syncthreads();
    red[j] = fmaxf(f1, f2);
    __syncthreads();
    for (int off = 128; off > 0; off >>= 1) {
        if (j < off) red[j] = fmaxf(red[j], red[j + off]);
        __syncthreads();
    }
    if (j == 0) Mfc = red[0];
    __syncthreads();
    red[j] = expf(f1 - Mfc) + expf(f2 - Mfc);
    __syncthreads();
    for (int off = 128; off > 0; off >>= 1) {
        if (j < off) red[j] += red[j + off];
        __syncthreads();
    }
    if (j == 0) {
        Sfc = red[0];
        g_loss[i] = (Msc + logf(Ssc)) - diag_sc;
        g_loss[NGRAPH + i] = (Mfc + logf(Sfc)) - diag_fc;
    }
}

// ---------------- final ----------------
__global__ void k_final(const float* __restrict__ fc2W, const float* __restrict__ fc2b,
                        float* __restrict__ out) {
    __shared__ float red[256];
    __shared__ float scalar;
    int t = threadIdx.x;
    red[t] = g_loss[t] + g_loss[NGRAPH + t];
    __syncthreads();
    for (int off = 128; off > 0; off >>= 1) {
        if (t < off) red[t] += red[t + off];
        __syncthreads();
    }
    if (t == 0) scalar = red[0] / (2.0f * NGRAPH);
    __syncthreads();
    float l0 = fc2b[0], l1 = fc2b[1];
    const float* z = &g_z[t * HID];
#pragma unroll 4
    for (int k = 0; k < HID; k++) {
        float zv = z[k];
        l0 = fmaf(zv, fc2W[2 * k], l0);
        l1 = fmaf(zv, fc2W[2 * k + 1], l1);
    }
    float m = fmaxf(l0, l1);
    float lse = m + logf(expf(l0 - m) + expf(l1 - m));
    out[2 * t] = l0 - lse + scalar;
    out[2 * t + 1] = l1 - lse + scalar;
}

// ---------------- host side ----------------
extern "C" void kernel_launch(void* const* d_in, const int* in_sizes, int n_in,
                              void* d_out, int out_size) {
    const float *sc_x = 0, *fc_x = 0, *sc_W = 0, *sc_b = 0, *fc_W = 0, *fc_b = 0;
    const float *fc1W = 0, *fc1b = 0, *fc2W = 0, *fc2b = 0;
    const int *sc_ei = 0, *fc_ei = 0, *batch = 0;
    for (int i = 0; i < n_in; i++) {
        long s = in_sizes[i];
        const void* p = d_in[i];
        if (s == (long)N_NODESC * HID) {
            if (!sc_x) sc_x = (const float*)p; else fc_x = (const float*)p;
        } else if (s == 2L * N_EDGESC) {
            if (!sc_ei) sc_ei = (const int*)p; else fc_ei = (const int*)p;
        } else if (s == N_NODESC) {
            batch = (const int*)p;
        } else if (s == (long)NLAYER * HID * HID) {
            if (!sc_W) sc_W = (const float*)p; else fc_W = (const float*)p;
        } else if (s == (long)NLAYER * HID) {
            if (!sc_b) sc_b = (const float*)p; else fc_b = (const float*)p;
        } else if (s == 2L * HID * HID) {
            fc1W = (const float*)p;
        } else if (s == HID) {
            fc1b = (const float*)p;
        } else if (s == 2L * HID) {
            fc2W = (const float*)p;
        } else if (s == 2) {
            fc2b = (const float*)p;
        }
    }
    cudaFuncSetAttribute(k_gemm_mma, cudaFuncAttributeMaxDynamicSharedMemorySize,
                         GEMM_SMEM);

    k_prep_x<<<dim3((N_NODESC * HID / 4 + 255) / 256, 2), 256>>>(
        (const float4*)sc_x, (const float4*)fc_x);
    k_prep_w<<<dim3((NLAYER * HID * HID + 255) / 256, 2), 256>>>(sc_W, fc_W);
    k_zero_counts<<<dim3((N_NODESC + 256) / 256, 2), 256>>>();
    k_hist<<<dim3(1024, 2), 256>>>(sc_ei, fc_ei);
    k_scan1<<<dim3(SCAN_BLOCKS, 2), 1024>>>();
    k_scan2<<<dim3(1, 2), 32>>>();
    k_scan3<<<dim3(SCAN_BLOCKS, 2), 1024>>>();
    k_bucket<<<dim3(1024, 2), 256>>>(sc_ei, fc_ei);
    for (int l = 0; l < NLAYER; ++l) {
        k_gemm_mma<<<dim3(148, 2), 256, GEMM_SMEM>>>(l, N_NODESC);
        k_agg<<<dim3((N_NODESC * 32 + 255) / 256, 2), 256>>>(sc_b, fc_b, l);
    }
    k_pool2<<<dim3(NGRAPH, 2), 128>>>(batch);
    k_head<<<NGRAPH, 128>>>(fc1W, fc1b);
    k_loss<<<NGRAPH, 256>>>();
    k_final<<<1, 256>>>(fc2W, fc2b, (float*)d_out);
}

// round 8
// speedup vs baseline: 1.9987x; 1.0143x over previous
#include <cuda_runtime.h>
#include <cuda_bf16.h>
#include <cuda_fp16.h>
#include <math.h>
#include <stdint.h>

#define N_NODESC 100000
#define N_EDGESC 1600000
#define HID 128
#define NGRAPH 256
#define NLAYER 3
#define SCAN_BLOCKS ((N_NODESC + 1023) / 1024)   // 98
#define NT64 ((N_NODESC + 63) / 64)              // 1563

// prep kernel block ranges
#define XB ((N_NODESC * HID / 4 + 255) / 256)    // 12500
#define WB ((NLAYER * HID * HID + 255) / 256)    // 192
#define ZB ((N_NODESC + 256) / 256)              // 392

// ---------------- scratch (static device globals; no allocation) ----------------
__device__ __half    g_h[2][(size_t)N_NODESC * HID];   // GEMM output (fp16)
__device__ uint32_t  g_xs[2][(size_t)N_NODESC * HID];  // activations, packed bf16 hi|lo
__device__ uint32_t  g_ws[2][NLAYER * HID * HID];      // W, packed bf16 hi|lo
__device__ float     g_dis[2][N_NODESC];
__device__ int       g_off[2][N_NODESC + 1];
__device__ int       g_cur[2][N_NODESC];
__device__ int2      g_ew[2][N_EDGESC];                // {src, enorm}
__device__ int       g_bsum[2][SCAN_BLOCKS + 1];
__device__ float     g_z[NGRAPH * HID];
__device__ float     g_scn[NGRAPH * HID];
__device__ float     g_fcn[NGRAPH * HID];
__device__ float     g_loss[2 * NGRAPH];

// ---------------- helpers ----------------
__device__ __forceinline__ uint32_t smem_u32(const void* p) {
    uint32_t a;
    asm("{ .reg .u64 t; cvta.to.shared.u64 t, %1; cvt.u32.u64 %0, t; }"
        : "=r"(a) : "l"(p));
    return a;
}
__device__ __forceinline__ uint32_t packsplit(float v) {
    __nv_bfloat16 h = __float2bfloat16_rn(v);
    float lo = v - __bfloat162float(h);
    __nv_bfloat16 l = __float2bfloat16_rn(lo);
    return (uint32_t)__bfloat16_as_ushort(h) |
           ((uint32_t)__bfloat16_as_ushort(l) << 16);
}
__device__ __forceinline__ float unpacksplit(uint32_t p) {
    return __bfloat162float(__ushort_as_bfloat16((unsigned short)(p & 0xffffu))) +
           __bfloat162float(__ushort_as_bfloat16((unsigned short)(p >> 16)));
}
#define LDSM_X4(r0, r1, r2, r3, addr) \
    asm volatile("ldmatrix.sync.aligned.m8n8.x4.shared.b16 {%0,%1,%2,%3}, [%4];" \
                 : "=r"(r0), "=r"(r1), "=r"(r2), "=r"(r3) : "r"(addr))
#define LDSM_X4T(r0, r1, r2, r3, addr) \
    asm volatile("ldmatrix.sync.aligned.m8n8.x4.trans.shared.b16 {%0,%1,%2,%3}, [%4];" \
                 : "=r"(r0), "=r"(r1), "=r"(r2), "=r"(r3) : "r"(addr))
#define MMA16816(c, a, b0, b1) \
    asm volatile("mma.sync.aligned.m16n8k16.row.col.f32.bf16.bf16.f32 " \
                 "{%0,%1,%2,%3}, {%4,%5,%6,%7}, {%8,%9}, {%0,%1,%2,%3};" \
                 : "+f"((c)[0]), "+f"((c)[1]), "+f"((c)[2]), "+f"((c)[3]) \
                 : "r"((a)[0]), "r"((a)[1]), "r"((a)[2]), "r"((a)[3]), \
                   "r"(b0), "r"(b1))

// ---------------- fused prep: x-split | w-split | zero counts ----------------
__global__ void k_prep(const float4* __restrict__ sc_x, const float4* __restrict__ fc_x,
                       const float* __restrict__ scW, const float* __restrict__ fcW) {
    int b = blockIdx.y;
    int bx = blockIdx.x;
    if (bx < XB) {
        const float4* src = b ? fc_x : sc_x;
        size_t i = (size_t)bx * 256 + threadIdx.x;
        if (i < (size_t)N_NODESC * HID / 4) {
            float4 v = src[i];
            ((uint4*)g_xs[b])[i] = make_uint4(packsplit(v.x), packsplit(v.y),
                                              packsplit(v.z), packsplit(v.w));
        }
    } else if (bx < XB + WB) {
        const float* W = b ? fcW : scW;
        int i = (bx - XB) * 256 + threadIdx.x;
        if (i < NLAYER * HID * HID) g_ws[b][i] = packsplit(W[i]);
    } else {
        int i = (bx - XB - WB) * 256 + threadIdx.x;
        if (i <= N_NODESC) g_off[b][i] = 0;
    }
}

// ---------------- CSR build ----------------
__global__ void k_hist(const int* __restrict__ sc_ei, const int* __restrict__ fc_ei) {
    int b = blockIdx.y;
    const int* dst = (b ? fc_ei : sc_ei) + N_EDGESC;
    for (int e = blockIdx.x * blockDim.x + threadIdx.x; e < N_EDGESC;
         e += gridDim.x * blockDim.x)
        atomicAdd(&g_off[b][dst[e]], 1);
}
__global__ void k_scan1() {
    __shared__ int ws[32];
    int b = blockIdx.y;
    int t = threadIdx.x;
    int lane = t & 31, w = t >> 5;
    int idx = blockIdx.x * 1024 + t;
    int v = (idx < N_NODESC) ? g_off[b][idx] : 0;
    if (idx < N_NODESC) g_dis[b][idx] = rsqrtf((float)v + 1.0f);
    int x = v;
#pragma unroll
    for (int off = 1; off < 32; off <<= 1) {
        int n = __shfl_up_sync(0xffffffffu, x, off);
        if (lane >= off) x += n;
    }
    if (lane == 31) ws[w] = x;
    __syncthreads();
    if (w == 0) {
        int y = ws[lane];
#pragma unroll
        for (int off = 1; off < 32; off <<= 1) {
            int n = __shfl_up_sync(0xffffffffu, y, off);
            if (lane >= off) y += n;
        }
        ws[lane] = y;
    }
    __syncthreads();
    int inc = x + ((w > 0) ? ws[w - 1] : 0);
    if (idx < N_NODESC) g_off[b][idx] = inc - v;
    if (t == 1023) g_bsum[b][blockIdx.x] = inc;
}
// scan3: each block reduces raw block sums [0, blockIdx.x) itself (kills scan2)
__global__ void k_scan3() {
    int b = blockIdx.y;
    int t = threadIdx.x;
    __shared__ int wsum[32];
    __shared__ int s_pref;
    int lane = t & 31, w = t >> 5;
    int v = (t < blockIdx.x) ? g_bsum[b][t] : 0;   // blockIdx.x <= 97 < 1024
#pragma unroll
    for (int off = 16; off > 0; off >>= 1)
        v += __shfl_down_sync(0xffffffffu, v, off);
    if (lane == 0) wsum[w] = v;
    __syncthreads();
    if (t == 0) {
        int s = 0;
#pragma unroll
        for (int i = 0; i < 32; i++) s += wsum[i];
        s_pref = s;
    }
    __syncthreads();
    int idx = blockIdx.x * 1024 + t;
    if (idx < N_NODESC) {
        int o = g_off[b][idx] + s_pref;
        g_off[b][idx] = o;
        g_cur[b][idx] = o;
    }
    if (blockIdx.x == 0 && t == 0) g_off[b][N_NODESC] = N_EDGESC;
}
__global__ void k_bucket(const int* __restrict__ sc_ei, const int* __restrict__ fc_ei) {
    int b = blockIdx.y;
    const int* src = (b ? fc_ei : sc_ei);
    const int* dst = src + N_EDGESC;
    for (int e = blockIdx.x * blockDim.x + threadIdx.x; e < N_EDGESC;
         e += gridDim.x * blockDim.x) {
        int d = dst[e];
        int s = src[e];
        int slot = atomicAdd(&g_cur[b][d], 1);
        float w = g_dis[b][s] * g_dis[b][d];
        g_ew[b][slot] = make_int2(s, __float_as_int(w));
    }
}

// ---------------- persistent tensor-core GEMM with A-prefetch ----------------
#define APITCH 136
#define BTILE_B (128 * APITCH * 2)     // 34816
#define ATILE_B (64 * APITCH * 2)      // 17408
#define OFF_BHI 0
#define OFF_BLO BTILE_B
#define OFF_AHI (2 * BTILE_B)
#define OFF_ALO (2 * BTILE_B + ATILE_B)
#define GEMM_SMEM (2 * BTILE_B + 2 * ATILE_B)   // 104448

__global__ void __launch_bounds__(256, 2)
k_gemm_mma(int layer, int nrows) {
    extern __shared__ char sm[];
    uint32_t base = smem_u32(sm);
    int b = blockIdx.y;
    int tid = threadIdx.x;
    const uint32_t* Xp = g_xs[b];
    const uint32_t* Wp = g_ws[b] + layer * HID * HID;
    __half* Hp = g_h[b];

    // ---- unpack W -> Bhi/Blo once per CTA ----
    for (int g = tid; g < 128 * 32; g += 256) {
        int k = g >> 5, q = g & 31;
        uint4 p = ((const uint4*)Wp)[k * 32 + q];
        uint32_t off = (uint32_t)(k * APITCH + q * 4) * 2u;
        *(uint2*)(sm + OFF_BHI + off) =
            make_uint2(__byte_perm(p.x, p.y, 0x5410), __byte_perm(p.z, p.w, 0x5410));
        *(uint2*)(sm + OFF_BLO + off) =
            make_uint2(__byte_perm(p.x, p.y, 0x7632), __byte_perm(p.z, p.w, 0x7632));
    }

    int w = tid >> 5, lane = tid & 31;
    int wm = w & 1, wn = w >> 1;            // 2 row-groups x 4 col-groups
    int rbase = wm * 32, cbase = wn * 32;
    int a_r = lane & 15, a_c = (lane >> 4) * 8;
    int b_kr = ((lane >> 3) & 1) * 8 + (lane & 7), b_c = (lane >> 4) * 8;

    uint4 pre[8];
    {   // preload first tile
        int r0 = blockIdx.x * 64;
#pragma unroll
        for (int i = 0; i < 8; ++i) {
            int g = tid + i * 256;
            int row = g >> 5, q = g & 31;
            int grow = r0 + row;
            pre[i] = (grow < nrows)
                ? ((const uint4*)(Xp + (size_t)grow * HID))[q]
                : make_uint4(0u, 0u, 0u, 0u);
        }
    }

    for (int tile = blockIdx.x; tile < NT64; tile += gridDim.x) {
        int r0 = tile * 64;
        __syncthreads();   // prev mainloop done before A overwrite (orders W STS too)
        // ---- convert prefetched regs -> Ahi/Alo ----
#pragma unroll
        for (int i = 0; i < 8; ++i) {
            int g = tid + i * 256;
            int row = g >> 5, q = g & 31;
            uint4 p = pre[i];
            uint32_t off = (uint32_t)(row * APITCH + q * 4) * 2u;
            *(uint2*)(sm + OFF_AHI + off) =
                make_uint2(__byte_perm(p.x, p.y, 0x5410), __byte_perm(p.z, p.w, 0x5410));
            *(uint2*)(sm + OFF_ALO + off) =
                make_uint2(__byte_perm(p.x, p.y, 0x7632), __byte_perm(p.z, p.w, 0x7632));
        }
        __syncthreads();

        // ---- prefetch next tile (latency hidden by mainloop) ----
        int next = tile + gridDim.x;
        if (next < NT64) {
            int nr0 = next * 64;
#pragma unroll
            for (int i = 0; i < 8; ++i) {
                int g = tid + i * 256;
                int row = g >> 5, q = g & 31;
                int grow = nr0 + row;
                pre[i] = (grow < nrows)
                    ? ((const uint4*)(Xp + (size_t)grow * HID))[q]
                    : make_uint4(0u, 0u, 0u, 0u);
            }
        }

        float acc[2][4][4];
#pragma unroll
        for (int m = 0; m < 2; m++)
#pragma unroll
            for (int n = 0; n < 4; n++)
#pragma unroll
                for (int c = 0; c < 4; c++) acc[m][n][c] = 0.f;

#pragma unroll
        for (int ks = 0; ks < 8; ++ks) {
            int k0 = ks * 16;
            uint32_t ahi[2][4], alo[2][4];
#pragma unroll
            for (int m = 0; m < 2; ++m) {
                uint32_t aoff =
                    (uint32_t)((rbase + m * 16 + a_r) * APITCH + k0 + a_c) * 2u;
                LDSM_X4(ahi[m][0], ahi[m][1], ahi[m][2], ahi[m][3], base + OFF_AHI + aoff);
                LDSM_X4(alo[m][0], alo[m][1], alo[m][2], alo[m][3], base + OFF_ALO + aoff);
            }
#pragma unroll
            for (int n2 = 0; n2 < 2; ++n2) {
                int n0 = cbase + n2 * 16;
                uint32_t boff = (uint32_t)((k0 + b_kr) * APITCH + n0 + b_c) * 2u;
                uint32_t bh0, bh1, bh2, bh3, bl0, bl1, bl2, bl3;
                LDSM_X4T(bh0, bh1, bh2, bh3, base + OFF_BHI + boff);
                LDSM_X4T(bl0, bl1, bl2, bl3, base + OFF_BLO + boff);
#pragma unroll
                for (int m = 0; m < 2; ++m) {
                    MMA16816(acc[m][n2 * 2], ahi[m], bh0, bh1);
                    MMA16816(acc[m][n2 * 2 + 1], ahi[m], bh2, bh3);
                    MMA16816(acc[m][n2 * 2], ahi[m], bl0, bl1);
                    MMA16816(acc[m][n2 * 2 + 1], ahi[m], bl2, bl3);
                    MMA16816(acc[m][n2 * 2], alo[m], bh0, bh1);
                    MMA16816(acc[m][n2 * 2 + 1], alo[m], bh2, bh3);
                }
            }
        }

        // ---- epilogue: write h as fp16 ----
#pragma unroll
        for (int m = 0; m < 2; ++m) {
            int rA = r0 + rbase + m * 16 + (lane >> 2);
            int rB = rA + 8;
#pragma unroll
            for (int ng = 0; ng < 4; ++ng) {
                int col = cbase + ng * 8 + (lane & 3) * 2;
                if (rA < nrows)
                    *(__half2*)(Hp + (size_t)rA * HID + col) =
                        __floats2half2_rn(acc[m][ng][0], acc[m][ng][1]);
                if (rB < nrows)
                    *(__half2*)(Hp + (size_t)rB * HID + col) =
                        __floats2half2_rn(acc[m][ng][2], acc[m][ng][3]);
            }
        }
    }
}

// ---------------- fused aggregation ----------------
__global__ void __launch_bounds__(256)
k_agg(const float* __restrict__ sc_b, const float* __restrict__ fc_b, int layer) {
    int b = blockIdx.y;
    int node = (blockIdx.x * blockDim.x + threadIdx.x) >> 5;
    int lane = threadIdx.x & 31;
    if (node >= N_NODESC) return;
    const __half* Hp = g_h[b];
    const int2* ew = g_ew[b];
    const float* bias = (b ? fc_b : sc_b) + layer * HID;
    float dd = g_dis[b][node];
    int beg = g_off[b][node], end = g_off[b][node + 1];
    float ax = 0.f, ay = 0.f, az = 0.f, aw = 0.f;
    int e = beg;
    for (; e + 3 < end; e += 4) {
        int2 p0 = ew[e], p1 = ew[e + 1], p2 = ew[e + 2], p3 = ew[e + 3];
        uint2 r0v = *(const uint2*)(Hp + (size_t)p0.x * HID + lane * 4);
        uint2 r1v = *(const uint2*)(Hp + (size_t)p1.x * HID + lane * 4);
        uint2 r2v = *(const uint2*)(Hp + (size_t)p2.x * HID + lane * 4);
        uint2 r3v = *(const uint2*)(Hp + (size_t)p3.x * HID + lane * 4);
        float w0 = __int_as_float(p0.y), w1 = __int_as_float(p1.y);
        float w2 = __int_as_float(p2.y), w3 = __int_as_float(p3.y);
        float2 f0 = __half22float2(*(__half2*)&r0v.x);
        float2 f1 = __half22float2(*(__half2*)&r0v.y);
        ax = fmaf(f0.x, w0, ax); ay = fmaf(f0.y, w0, ay);
        az = fmaf(f1.x, w0, az); aw = fmaf(f1.y, w0, aw);
        f0 = __half22float2(*(__half2*)&r1v.x);
        f1 = __half22float2(*(__half2*)&r1v.y);
        ax = fmaf(f0.x, w1, ax); ay = fmaf(f0.y, w1, ay);
        az = fmaf(f1.x, w1, az); aw = fmaf(f1.y, w1, aw);
        f0 = __half22float2(*(__half2*)&r2v.x);
        f1 = __half22float2(*(__half2*)&r2v.y);
        ax = fmaf(f0.x, w2, ax); ay = fmaf(f0.y, w2, ay);
        az = fmaf(f1.x, w2, az); aw = fmaf(f1.y, w2, aw);
        f0 = __half22float2(*(__half2*)&r3v.x);
        f1 = __half22float2(*(__half2*)&r3v.y);
        ax = fmaf(f0.x, w3, ax); ay = fmaf(f0.y, w3, ay);
        az = fmaf(f1.x, w3, az); aw = fmaf(f1.y, w3, aw);
    }
    for (; e < end; ++e) {
        int2 p0 = ew[e];
        float w0 = __int_as_float(p0.y);
        uint2 r0v = *(const uint2*)(Hp + (size_t)p0.x * HID + lane * 4);
        float2 f0 = __half22float2(*(__half2*)&r0v.x);
        float2 f1 = __half22float2(*(__half2*)&r0v.y);
        ax = fmaf(f0.x, w0, ax); ay = fmaf(f0.y, w0, ay);
        az = fmaf(f1.x, w0, az); aw = fmaf(f1.y, w0, aw);
    }
    uint2 rs = *(const uint2*)(Hp + (size_t)node * HID + lane * 4);
    float2 s0 = __half22float2(*(__half2*)&rs.x);
    float2 s1 = __half22float2(*(__half2*)&rs.y);
    float sn = dd * dd;
    float4 bb = *(const float4*)(bias + lane * 4);
    ax = fmaxf(fmaf(s0.x, sn, ax) + bb.x, 0.f);
    ay = fmaxf(fmaf(s0.y, sn, ay) + bb.y, 0.f);
    az = fmaxf(fmaf(s1.x, sn, az) + bb.z, 0.f);
    aw = fmaxf(fmaf(s1.y, sn, aw) + bb.w, 0.f);
    uint4 st = make_uint4(packsplit(ax), packsplit(ay), packsplit(az), packsplit(aw));
    *(uint4*)(g_xs[b] + (size_t)node * HID + lane * 4) = st;
}

// ---------------- fused pool + head (block per graph) ----------------
__global__ void __launch_bounds__(128)
k_headpool(const int* __restrict__ batch, const float* __restrict__ fc1W,
           const float* __restrict__ fc1b) {
    int g = blockIdx.x, t = threadIdx.x;  // 128 threads
    __shared__ int s_lo, s_hi;
    if (t == 0) {
        int lo = 0, hi = N_NODESC;
        while (lo < hi) { int m = (lo + hi) >> 1; if (batch[m] < g) lo = m + 1; else hi = m; }
        s_lo = lo;
    }
    if (t == 32) {
        int lo = 0, hi = N_NODESC;
        while (lo < hi) { int m = (lo + hi) >> 1; if (batch[m] < g + 1) lo = m + 1; else hi = m; }
        s_hi = lo;
    }
    __syncthreads();
    int lo = s_lo, hi = s_hi;
    const uint32_t* X0 = g_xs[0];
    const uint32_t* X1 = g_xs[1];
    float acc_sc = 0.f, acc_fc = 0.f;
    int n = lo;
    for (; n + 1 < hi; n += 2) {
        acc_sc += unpacksplit(X0[(size_t)n * HID + t]) +
                  unpacksplit(X0[(size_t)(n + 1) * HID + t]);
        acc_fc += unpacksplit(X1[(size_t)n * HID + t]) +
                  unpacksplit(X1[(size_t)(n + 1) * HID + t]);
    }
    for (; n < hi; ++n) {
        acc_sc += unpacksplit(X0[(size_t)n * HID + t]);
        acc_fc += unpacksplit(X1[(size_t)n * HID + t]);
    }

    __shared__ float s[256];
    __shared__ float red[128];
    __shared__ float inv_ns, inv_nf;
    s[t] = acc_sc;
    s[128 + t] = acc_fc;
    __syncthreads();
    red[t] = s[t] * s[t];
    __syncthreads();
    for (int off = 64; off > 0; off >>= 1) {
        if (t < off) red[t] += red[t + off];
        __syncthreads();
    }
    if (t == 0) inv_ns = 1.0f / fmaxf(sqrtf(red[0]), 1e-12f);
    __syncthreads();
    red[t] = s[128 + t] * s[128 + t];
    __syncthreads();
    for (int off = 64; off > 0; off >>= 1) {
        if (t < off) red[t] += red[t + off];
        __syncthreads();
    }
    if (t == 0) inv_nf = 1.0f / fmaxf(sqrtf(red[0]), 1e-12f);
    __syncthreads();
    float acc = 0.f;
#pragma unroll 8
    for (int k = 0; k < 256; k++) acc = fmaf(s[k], fc1W[k * HID + t], acc);
    acc += fc1b[t];
    g_z[g * HID + t] = fmaxf(acc, 0.f);
    g_scn[g * HID + t] = s[t] * inv_ns;
    g_fcn[g * HID + t] = s[128 + t] * inv_nf;
}

// ---------------- contrastive row losses ----------------
__global__ void k_loss() {
    int i = blockIdx.x, j = threadIdx.x;
    __shared__ float sni[HID], fni[HID];
    __shared__ float red[256];
    __shared__ float diag_sc, diag_fc, Msc, Mfc, Ssc, Sfc;
    if (j < HID) { sni[j] = g_scn[i * HID + j]; fni[j] = g_fcn[i * HID + j]; }
    __syncthreads();
    float dsf = 0.f, dss = 0.f, dfs = 0.f, dff = 0.f;
    const float* srow = &g_scn[j * HID];
    const float* frow = &g_fcn[j * HID];
#pragma unroll 4
    for (int k = 0; k < HID; k++) {
        float sj = srow[k], fj = frow[k], si = sni[k], fi = fni[k];
        dsf = fmaf(si, fj, dsf);
        dss = fmaf(si, sj, dss);
        dfs = fmaf(fi, sj, dfs);
        dff = fmaf(fi, fj, dff);
    }
    const float tt = 2.0f;
    float e1 = dsf * tt;
    float e2 = (j == i) ? 0.f : 0.8f * tt * dss;
    float f1 = dfs * tt;
    float f2 = (j == i) ? 0.f : 0.8f * tt * dff;
    if (j == i) { diag_sc = e1; diag_fc = f1; }
    red[j] = fmaxf(e1, e2);
    __syncthreads();
    for (int off = 128; off > 0; off >>= 1) {
        if (j < off) red[j] = fmaxf(red[j], red[j + off]);
        __syncthreads();
    }
    if (j == 0) Msc = red[0];
    __syncthreads();
    red[j] = expf(e1 - Msc) + expf(e2 - Msc);
    __syncthreads();
    for (int off = 128; off > 0; off >>= 1) {
        if (j < off) red[j] += red[j + off];
        __syncthreads();
    }
    if (j == 0) Ssc = red[0];
    __syncthreads();
    red[j] = fmaxf(f1, f2);
    __syncthreads();
    for (int off = 128; off > 0; off >>= 1) {
        if (j < off) red[j] = fmaxf(red[j], red[j + off]);
        __syncthreads();
    }
    if (j == 0) Mfc = red[0];
    __syncthreads();
    red[j] = expf(f1 - Mfc) + expf(f2 - Mfc);
    __syncthreads();
    for (int off = 128; off > 0; off >>= 1) {
        if (j < off) red[j] += red[j + off];
        __syncthreads();
    }
    if (j == 0) {
        Sfc = red[0];
        g_loss[i] = (Msc + logf(Ssc)) - diag_sc;
        g_loss[NGRAPH + i] = (Mfc + logf(Sfc)) - diag_fc;
    }
}

// ---------------- final ----------------
__global__ void k_final(const float* __restrict__ fc2W, const float* __restrict__ fc2b,
                        float* __restrict__ out) {
    __shared__ float red[256];
    __shared__ float scalar;
    int t = threadIdx.x;
    red[t] = g_loss[t] + g_loss[NGRAPH + t];
    __syncthreads();
    for (int off = 128; off > 0; off >>= 1) {
        if (t < off) red[t] += red[t + off];
        __syncthreads();
    }
    if (t == 0) scalar = red[0] / (2.0f * NGRAPH);
    __syncthreads();
    float l0 = fc2b[0], l1 = fc2b[1];
    const float* z = &g_z[t * HID];
#pragma unroll 4
    for (int k = 0; k < HID; k++) {
        float zv = z[k];
        l0 = fmaf(zv, fc2W[2 * k], l0);
        l1 = fmaf(zv, fc2W[2 * k + 1], l1);
    }
    float m = fmaxf(l0, l1);
    float lse = m + logf(expf(l0 - m) + expf(l1 - m));
    out[2 * t] = l0 - lse + scalar;
    out[2 * t + 1] = l1 - lse + scalar;
}

// ---------------- host side ----------------
extern "C" void kernel_launch(void* const* d_in, const int* in_sizes, int n_in,
                              void* d_out, int out_size) {
    const float *sc_x = 0, *fc_x = 0, *sc_W = 0, *sc_b = 0, *fc_W = 0, *fc_b = 0;
    const float *fc1W = 0, *fc1b = 0, *fc2W = 0, *fc2b = 0;
    const int *sc_ei = 0, *fc_ei = 0, *batch = 0;
    for (int i = 0; i < n_in; i++) {
        long s = in_sizes[i];
        const void* p = d_in[i];
        if (s == (long)N_NODESC * HID) {
            if (!sc_x) sc_x = (const float*)p; else fc_x = (const float*)p;
        } else if (s == 2L * N_EDGESC) {
            if (!sc_ei) sc_ei = (const int*)p; else fc_ei = (const int*)p;
        } else if (s == N_NODESC) {
            batch = (const int*)p;
        } else if (s == (long)NLAYER * HID * HID) {
            if (!sc_W) sc_W = (const float*)p; else fc_W = (const float*)p;
        } else if (s == (long)NLAYER * HID) {
            if (!sc_b) sc_b = (const float*)p; else fc_b = (const float*)p;
        } else if (s == 2L * HID * HID) {
            fc1W = (const float*)p;
        } else if (s == HID) {
            fc1b = (const float*)p;
        } else if (s == 2L * HID) {
            fc2W = (const float*)p;
        } else if (s == 2) {
            fc2b = (const float*)p;
        }
    }
    cudaFuncSetAttribute(k_gemm_mma, cudaFuncAttributeMaxDynamicSharedMemorySize,
                         GEMM_SMEM);

    k_prep<<<dim3(XB + WB + ZB, 2), 256>>>((const float4*)sc_x, (const float4*)fc_x,
                                           sc_W, fc_W);
    k_hist<<<dim3(1024, 2), 256>>>(sc_ei, fc_ei);
    k_scan1<<<dim3(SCAN_BLOCKS, 2), 1024>>>();
    k_scan3<<<dim3(SCAN_BLOCKS, 2), 1024>>>();
    k_bucket<<<dim3(1024, 2), 256>>>(sc_ei, fc_ei);
    for (int l = 0; l < NLAYER; ++l) {
        k_gemm_mma<<<dim3(148, 2), 256, GEMM_SMEM>>>(l, N_NODESC);
        k_agg<<<dim3((N_NODESC * 32 + 255) / 256, 2), 256>>>(sc_b, fc_b, l);
    }
    k_headpool<<<NGRAPH, 128>>>(batch, fc1W, fc1b);
    k_loss<<<NGRAPH, 256>>>();
    k_final<<<1, 256>>>(fc2W, fc2b, (float*)d_out);
}